// round 10
// baseline (speedup 1.0000x reference)
#include <cuda_runtime.h>
#include <cuda_bf16.h>
#include <mma.h>
#include <cstdint>

using namespace nvcuda;

#define B 512
#define T 256
#define C 384
#define HS 64
#define BT (B * T)

// ---------------- scratch -----------------------------------------------------
__device__ __nv_bfloat16 g_Qhi[BT * HS];
__device__ __nv_bfloat16 g_Qlo[BT * HS];
__device__ __nv_bfloat16 g_Khi[BT * HS];
__device__ __nv_bfloat16 g_Klo[BT * HS];
__device__ __nv_bfloat16 g_Vhi[BT * HS];
__device__ __nv_bfloat16 g_Vlo[BT * HS];
// bf16 split weights, [k][n] row-major, n in [0,192) = [Wq|Wk|Wv] columns
__device__ __nv_bfloat16 g_Whi[C * 192];
__device__ __nv_bfloat16 g_Wlo[C * 192];

// ---------------- W bf16 split kernel ------------------------------------------
__global__ void convert_w(const float* __restrict__ Wq,
                          const float* __restrict__ Wk,
                          const float* __restrict__ Wv)
{
    int k = blockIdx.x;     // 0..383
    int n = threadIdx.x;    // 0..191
    const float* W = (n < 64) ? Wq : ((n < 128) ? Wk : Wv);
    float w = W[(size_t)k * HS + (n & 63)];
    __nv_bfloat16 hi = __float2bfloat16(w);
    g_Whi[(size_t)k * 192 + n] = hi;
    g_Wlo[(size_t)k * 192 + n] = __float2bfloat16(w - __bfloat162float(hi));
}

__device__ __forceinline__ void cvt_store4(char* hiBase, char* loBase,
                                           int elemOff, float4 v)
{
    __nv_bfloat16* ah = (__nv_bfloat16*)hiBase + elemOff;
    __nv_bfloat16* al = (__nv_bfloat16*)loBase + elemOff;
    __nv_bfloat16 h0 = __float2bfloat16(v.x);
    __nv_bfloat16 h1 = __float2bfloat16(v.y);
    __nv_bfloat16 h2 = __float2bfloat16(v.z);
    __nv_bfloat16 h3 = __float2bfloat16(v.w);
    ah[0] = h0; ah[1] = h1; ah[2] = h2; ah[3] = h3;
    al[0] = __float2bfloat16(v.x - __bfloat162float(h0));
    al[1] = __float2bfloat16(v.y - __bfloat162float(h1));
    al[2] = __float2bfloat16(v.z - __bfloat162float(h2));
    al[3] = __float2bfloat16(v.w - __bfloat162float(h3));
}

// ---------------- QKV GEMM: WMMA bf16 3-product split, double-buffered --------
// 512 threads = 16 warps (4M x 4N). CTA tile 128x192, BK=32, 12 chunks.
// W loaded pre-split (bf16 hi/lo); x converted inline; output written bf16 hi/lo.
static constexpr int A_LD = 40;
static constexpr int B_LD = 200;
static constexpr int OFF_AHI = 0;          // 128*40*2 = 10240
static constexpr int OFF_ALO = 10240;
static constexpr int OFF_BHI = 20480;      // 32*200*2 = 12800
static constexpr int OFF_BLO = 33280;
static constexpr int STAGE   = 46080;
static constexpr int GEMM_SMEM_TOTAL = 2 * STAGE;   // 92160

__global__ __launch_bounds__(512, 1) void qkv_gemm_wmma(const float* __restrict__ x)
{
    extern __shared__ char smem[];
    const int tid = threadIdx.x;
    const int wid = tid >> 5;
    const int warp_m = wid >> 2;
    const int warp_n = wid & 3;
    const int rowBase = blockIdx.x * 128;

    // x: 128 rows x 8 float4 = 1024 -> 2/thread
    const int xr_r[2] = { (tid + 0) >> 3, (tid + 512) >> 3 };
    const int xr_c[2] = { (tid + 0) & 7,  (tid + 512) & 7 };
    // W bf16 hi+lo: 2 x 768 uint4 = 1536 -> 3/thread
    int wb_r[3], wb_u[3];
    const __nv_bfloat16* wb_src[3];
    int wb_dst[3];
#pragma unroll
    for (int t = 0; t < 3; t++) {
        int f = tid + t * 512;
        int g = (f < 768) ? f : (f - 768);
        wb_r[t] = g / 24;
        wb_u[t] = g - wb_r[t] * 24;
        wb_src[t] = (f < 768) ? g_Whi : g_Wlo;
        wb_dst[t] = (f < 768) ? OFF_BHI : OFF_BLO;
    }

    wmma::fragment<wmma::accumulator, 16, 16, 16, float> acc[2][3];
#pragma unroll
    for (int i = 0; i < 2; i++)
#pragma unroll
        for (int j = 0; j < 3; j++) wmma::fill_fragment(acc[i][j], 0.0f);

    // ---- prologue: chunk 0 into stage 0 ----
    {
        char* st = smem;
#pragma unroll
        for (int t = 0; t < 2; t++) {
            float4 v = *(const float4*)(x + (size_t)(rowBase + xr_r[t]) * C + xr_c[t] * 4);
            cvt_store4(st + OFF_AHI, st + OFF_ALO, xr_r[t] * A_LD + xr_c[t] * 4, v);
        }
#pragma unroll
        for (int t = 0; t < 3; t++) {
            *(uint4*)(st + wb_dst[t] + (wb_r[t] * B_LD + wb_u[t] * 8) * 2) =
                *(const uint4*)(wb_src[t] + (size_t)wb_r[t] * 192 + wb_u[t] * 8);
        }
    }
    __syncthreads();

    for (int c = 0; c < 12; c++) {
        char* st  = smem + (c & 1) * STAGE;
        char* nst = smem + ((c + 1) & 1) * STAGE;
        const int k1 = (c + 1) * 32;
        const bool more = (c + 1 < 12);

        // global prefetch of chunk c+1
        float4 xr[2];
        uint4 wr[3];
        if (more) {
#pragma unroll
            for (int t = 0; t < 2; t++)
                xr[t] = *(const float4*)(x + (size_t)(rowBase + xr_r[t]) * C + k1 + xr_c[t] * 4);
#pragma unroll
            for (int t = 0; t < 3; t++)
                wr[t] = *(const uint4*)(wb_src[t] + (size_t)(k1 + wb_r[t]) * 192 + wb_u[t] * 8);
        }

        // compute chunk c
        const __nv_bfloat16* Ahi = (const __nv_bfloat16*)(st + OFF_AHI);
        const __nv_bfloat16* Alo = (const __nv_bfloat16*)(st + OFF_ALO);
        const __nv_bfloat16* Bhi = (const __nv_bfloat16*)(st + OFF_BHI);
        const __nv_bfloat16* Blo = (const __nv_bfloat16*)(st + OFF_BLO);
#pragma unroll
        for (int ks = 0; ks < 2; ks++) {
            wmma::fragment<wmma::matrix_a, 16, 16, 16, __nv_bfloat16, wmma::row_major> ah[2], al[2];
#pragma unroll
            for (int i = 0; i < 2; i++) {
                wmma::load_matrix_sync(ah[i], Ahi + (warp_m * 32 + i * 16) * A_LD + ks * 16, A_LD);
                wmma::load_matrix_sync(al[i], Alo + (warp_m * 32 + i * 16) * A_LD + ks * 16, A_LD);
            }
#pragma unroll
            for (int j = 0; j < 3; j++) {
                int col = warp_n * 48 + j * 16;
                wmma::fragment<wmma::matrix_b, 16, 16, 16, __nv_bfloat16, wmma::row_major> bh, bl;
                wmma::load_matrix_sync(bh, Bhi + ks * 16 * B_LD + col, B_LD);
                wmma::load_matrix_sync(bl, Blo + ks * 16 * B_LD + col, B_LD);
#pragma unroll
                for (int i = 0; i < 2; i++) {
                    wmma::mma_sync(acc[i][j], ah[i], bh, acc[i][j]);
                    wmma::mma_sync(acc[i][j], ah[i], bl, acc[i][j]);
                    wmma::mma_sync(acc[i][j], al[i], bh, acc[i][j]);
                }
            }
        }

        if (more) {
#pragma unroll
            for (int t = 0; t < 2; t++)
                cvt_store4(nst + OFF_AHI, nst + OFF_ALO,
                           xr_r[t] * A_LD + xr_c[t] * 4, xr[t]);
#pragma unroll
            for (int t = 0; t < 3; t++)
                *(uint4*)(nst + wb_dst[t] + (wb_r[t] * B_LD + wb_u[t] * 8) * 2) = wr[t];
        }
        __syncthreads();
    }

    // ---- epilogue: stage fp32 in smem, write bf16 hi/lo, 2 passes of 64 rows --
    float* Sb = (float*)smem;
    for (int p = 0; p < 2; p++) {
        __syncthreads();
        if ((warp_m >> 1) == p) {
#pragma unroll
            for (int i = 0; i < 2; i++)
#pragma unroll
                for (int j = 0; j < 3; j++)
                    wmma::store_matrix_sync(
                        Sb + ((warp_m & 1) * 32 + i * 16) * 192 + warp_n * 48 + j * 16,
                        acc[i][j], 192, wmma::mem_row_major);
        }
        __syncthreads();
#pragma unroll
        for (int t = 0; t < 12; t++) {
            int f = tid + t * 512;       // 0..6143 pairs
            int r = f / 96;
            int pc = f - r * 96;
            int cc = pc * 2;             // 0..190, even
            float2 v = *(const float2*)(Sb + r * 192 + cc);
            __nv_bfloat16* dhi = (cc < 64) ? g_Qhi : ((cc < 128) ? g_Khi : g_Vhi);
            __nv_bfloat16* dlo = (cc < 64) ? g_Qlo : ((cc < 128) ? g_Klo : g_Vlo);
            int col = cc & 63;
            size_t off = (size_t)(rowBase + p * 64 + r) * HS + col;
            __nv_bfloat16 h0 = __float2bfloat16(v.x);
            __nv_bfloat16 h1 = __float2bfloat16(v.y);
            __nv_bfloat162 hp; hp.x = h0; hp.y = h1;
            __nv_bfloat162 lp;
            lp.x = __float2bfloat16(v.x - __bfloat162float(h0));
            lp.y = __float2bfloat16(v.y - __bfloat162float(h1));
            *(__nv_bfloat162*)(dhi + off) = hp;
            *(__nv_bfloat162*)(dlo + off) = lp;
        }
    }
}

// ---------------- attention: WMMA flash-style, pre-split bf16 inputs ----------
static constexpr int LDH = 72;
static constexpr int AOF_QHI = 0;              // 128*72*2 = 18432
static constexpr int AOF_QLO = 18432;
static constexpr int AOF_KHI = 36864;          // 64*72*2 = 9216
static constexpr int AOF_KLO = 46080;
static constexpr int AOF_VHI = 55296;
static constexpr int AOF_VLO = 64512;
static constexpr int AOF_S   = 73728;          // 128*72*4 = 36864
static constexpr int AOF_PHI = 110592;
static constexpr int AOF_PLO = 129024;
static constexpr int AOF_L   = 147456;
static constexpr int ATTN_SMEM = 147968;

__global__ __launch_bounds__(512, 1) void attn_wmma(float* __restrict__ out)
{
    extern __shared__ char smem[];
    __nv_bfloat16* Qhi = (__nv_bfloat16*)(smem + AOF_QHI);
    __nv_bfloat16* Qlo = (__nv_bfloat16*)(smem + AOF_QLO);
    __nv_bfloat16* Khi = (__nv_bfloat16*)(smem + AOF_KHI);
    __nv_bfloat16* Klo = (__nv_bfloat16*)(smem + AOF_KLO);
    __nv_bfloat16* Vhi = (__nv_bfloat16*)(smem + AOF_VHI);
    __nv_bfloat16* Vlo = (__nv_bfloat16*)(smem + AOF_VLO);
    float*         S   = (float*)(smem + AOF_S);
    __nv_bfloat16* Phi = (__nv_bfloat16*)(smem + AOF_PHI);
    __nv_bfloat16* Plo = (__nv_bfloat16*)(smem + AOF_PLO);
    float*         lbuf = (float*)(smem + AOF_L);

    const int qt  = blockIdx.x;
    const int b   = blockIdx.y;
    const int i0  = qt * 128;
    const int tid = threadIdx.x;
    const int wid = tid >> 5;
    const int rt  = wid >> 1;
    const int cp  = wid & 1;

    if (tid < 128) lbuf[tid] = 0.0f;

    // load Q tile [128 x 64] hi+lo: 2048 uint4, 4/thread
    {
        const uint4* Qhig = (const uint4*)(g_Qhi + ((size_t)b * T + i0) * HS);
        const uint4* Qlog = (const uint4*)(g_Qlo + ((size_t)b * T + i0) * HS);
#pragma unroll
        for (int t = 0; t < 4; t++) {
            int f = tid + t * 512;
            int g = f & 1023;
            int r = g >> 3, c8 = g & 7;
            __nv_bfloat16* dst = (f < 1024) ? Qhi : Qlo;
            const uint4* src = (f < 1024) ? Qhig : Qlog;
            *(uint4*)(dst + r * LDH + c8 * 8) = src[g];
        }
    }
    __syncthreads();

    wmma::fragment<wmma::accumulator, 16, 16, 16, float> oacc[2];
    wmma::fill_fragment(oacc[0], 0.0f);
    wmma::fill_fragment(oacc[1], 0.0f);

    const float log2e_scale = 1.4426950408889634f * 0.125f;
    const int nkt = qt == 0 ? 2 : 4;
    const int i_glob = i0 + (tid >> 2);
    const int r_exp  = tid >> 2;
    const int cg     = tid & 3;

    for (int kt = 0; kt < nkt; kt++) {
        const int j0 = kt * 64;

        // load K,V tile hi+lo: 4 x 512 uint4 = 2048, 4/thread
        {
            const uint4* srcs[4] = {
                (const uint4*)(g_Khi + ((size_t)b * T + j0) * HS),
                (const uint4*)(g_Klo + ((size_t)b * T + j0) * HS),
                (const uint4*)(g_Vhi + ((size_t)b * T + j0) * HS),
                (const uint4*)(g_Vlo + ((size_t)b * T + j0) * HS)
            };
            __nv_bfloat16* dsts[4] = { Khi, Klo, Vhi, Vlo };
#pragma unroll
            for (int t = 0; t < 4; t++) {
                int f = tid + t * 512;
                int sel = f >> 9;
                int g = f & 511;
                int r = g >> 3, c8 = g & 7;
                *(uint4*)(dsts[sel] + r * LDH + c8 * 8) = srcs[sel][g];
            }
        }
        __syncthreads();

        // ---- S = Q K^T ----
#pragma unroll
        for (int f = 0; f < 2; f++) {
            const int n = cp * 32 + f * 16;
            wmma::fragment<wmma::accumulator, 16, 16, 16, float> sacc;
            wmma::fill_fragment(sacc, 0.0f);
#pragma unroll
            for (int ks = 0; ks < 4; ks++) {
                wmma::fragment<wmma::matrix_a, 16, 16, 16, __nv_bfloat16, wmma::row_major> ah, al;
                wmma::fragment<wmma::matrix_b, 16, 16, 16, __nv_bfloat16, wmma::col_major> bh, bl;
                wmma::load_matrix_sync(ah, Qhi + rt * 16 * LDH + ks * 16, LDH);
                wmma::load_matrix_sync(al, Qlo + rt * 16 * LDH + ks * 16, LDH);
                wmma::load_matrix_sync(bh, Khi + n * LDH + ks * 16, LDH);
                wmma::load_matrix_sync(bl, Klo + n * LDH + ks * 16, LDH);
                wmma::mma_sync(sacc, ah, bh, sacc);
                wmma::mma_sync(sacc, ah, bl, sacc);
                wmma::mma_sync(sacc, al, bh, sacc);
            }
            wmma::store_matrix_sync(S + rt * 16 * LDH + n, sacc, LDH,
                                    wmma::mem_row_major);
        }
        __syncthreads();

        // ---- exp + causal mask + row sums + P bf16 split ----
        {
            float* srow = S + r_exp * LDH + cg * 16;
            __nv_bfloat16* ph = Phi + r_exp * LDH + cg * 16;
            __nv_bfloat16* pl = Plo + r_exp * LDH + cg * 16;
            float ps = 0.0f;
#pragma unroll
            for (int c = 0; c < 16; c++) {
                int j = j0 + cg * 16 + c;
                float p = (j <= i_glob) ? exp2f(srow[c] * log2e_scale) : 0.0f;
                ps += p;
                __nv_bfloat16 hi = __float2bfloat16(p);
                ph[c] = hi;
                pl[c] = __float2bfloat16(p - __bfloat162float(hi));
            }
            ps += __shfl_xor_sync(0xFFFFFFFFu, ps, 1);
            ps += __shfl_xor_sync(0xFFFFFFFFu, ps, 2);
            if (cg == 0) lbuf[r_exp] += ps;
        }
        __syncthreads();

        // ---- O += P V ----
#pragma unroll
        for (int ks = 0; ks < 4; ks++) {
            wmma::fragment<wmma::matrix_a, 16, 16, 16, __nv_bfloat16, wmma::row_major> ah, al;
            wmma::load_matrix_sync(ah, Phi + rt * 16 * LDH + ks * 16, LDH);
            wmma::load_matrix_sync(al, Plo + rt * 16 * LDH + ks * 16, LDH);
#pragma unroll
            for (int f = 0; f < 2; f++) {
                const int n = cp * 32 + f * 16;
                wmma::fragment<wmma::matrix_b, 16, 16, 16, __nv_bfloat16, wmma::row_major> bh, bl;
                wmma::load_matrix_sync(bh, Vhi + ks * 16 * LDH + n, LDH);
                wmma::load_matrix_sync(bl, Vlo + ks * 16 * LDH + n, LDH);
                wmma::mma_sync(oacc[f], ah, bh, oacc[f]);
                wmma::mma_sync(oacc[f], ah, bl, oacc[f]);
                wmma::mma_sync(oacc[f], al, bh, oacc[f]);
            }
        }
        __syncthreads();
    }

    // ---- epilogue: normalize + write ----
#pragma unroll
    for (int f = 0; f < 2; f++) {
        const int n = cp * 32 + f * 16;
        wmma::store_matrix_sync(S + rt * 16 * LDH + n, oacc[f], LDH,
                                wmma::mem_row_major);
    }
    __syncthreads();
    {
        const float inv = 1.0f / lbuf[r_exp];
        const float* srow = S + r_exp * LDH + cg * 16;
        float* og = out + ((size_t)b * T + i0 + r_exp) * HS + cg * 16;
#pragma unroll
        for (int c4 = 0; c4 < 4; c4++) {
            float4 v = *(const float4*)(srow + c4 * 4);
            *(float4*)(og + c4 * 4) =
                make_float4(v.x * inv, v.y * inv, v.z * inv, v.w * inv);
        }
    }
}

// ---------------- launch --------------------------------------------------------
extern "C" void kernel_launch(void* const* d_in, const int* in_sizes, int n_in,
                              void* d_out, int out_size)
{
    (void)in_sizes; (void)n_in; (void)out_size;
    const float* x  = (const float*)d_in[0];
    const float* Wq = (const float*)d_in[1];
    const float* Wk = (const float*)d_in[2];
    const float* Wv = (const float*)d_in[3];
    float* out = (float*)d_out;

    convert_w<<<C, 192>>>(Wq, Wk, Wv);

    cudaFuncSetAttribute(qkv_gemm_wmma, cudaFuncAttributeMaxDynamicSharedMemorySize,
                         GEMM_SMEM_TOTAL);
    qkv_gemm_wmma<<<BT / 128, 512, GEMM_SMEM_TOTAL>>>(x);

    cudaFuncSetAttribute(attn_wmma, cudaFuncAttributeMaxDynamicSharedMemorySize,
                         ATTN_SMEM);
    dim3 agrid(2, B);
    attn_wmma<<<agrid, 512, ATTN_SMEM>>>(out);
}

// round 11
// speedup vs baseline: 1.6631x; 1.6631x over previous
#include <cuda_runtime.h>
#include <cuda_fp16.h>
#include <mma.h>
#include <cstdint>

using namespace nvcuda;

#define B 512
#define T 256
#define C 384
#define HS 64
#define BT (B * T)

// ---------------- scratch -----------------------------------------------------
__device__ __half g_Qf [BT * HS];          // Q single fp16
__device__ __half g_Khi[BT * HS];          // K split fp16
__device__ __half g_Klo[BT * HS];
__device__ __half g_Vhi[BT * HS];          // V split fp16
__device__ __half g_Vlo[BT * HS];
// fp16 split weights, [k][n] row-major, n in [0,192) = [Wq|Wk|Wv] columns
__device__ __half g_Whi[C * 192];
__device__ __half g_Wlo[C * 192];

// ---------------- W fp16 split kernel ------------------------------------------
__global__ void convert_w(const float* __restrict__ Wq,
                          const float* __restrict__ Wk,
                          const float* __restrict__ Wv)
{
    int k = blockIdx.x;     // 0..383
    int n = threadIdx.x;    // 0..191
    const float* W = (n < 64) ? Wq : ((n < 128) ? Wk : Wv);
    float w = W[(size_t)k * HS + (n & 63)];
    __half hi = __float2half(w);
    g_Whi[(size_t)k * 192 + n] = hi;
    g_Wlo[(size_t)k * 192 + n] = __float2half(w - __half2float(hi));
}

// convert float4 -> 4 single fp16, store 8 bytes
__device__ __forceinline__ void cvt_store4_h(char* base, int elemOff, float4 v)
{
    __half2 h01 = __floats2half2_rn(v.x, v.y);
    __half2 h23 = __floats2half2_rn(v.z, v.w);
    uint2 u;
    u.x = *(uint32_t*)&h01;
    u.y = *(uint32_t*)&h23;
    *(uint2*)((__half*)base + elemOff) = u;
}

// ---------------- QKV GEMM: WMMA fp16 2-product (x single, W split) -----------
// 512 threads = 16 warps (4M x 4N). CTA tile 128x192, BK=32, 12 chunks.
static constexpr int A_LD = 40;
static constexpr int B_LD = 200;
static constexpr int OFF_A   = 0;          // 128*40*2 = 10240
static constexpr int OFF_BHI = 10240;      // 32*200*2 = 12800
static constexpr int OFF_BLO = 23040;
static constexpr int STAGE   = 35840;
static constexpr int GEMM_SMEM_TOTAL = 2 * STAGE + 98304 > 2 * STAGE ? 98304 : 2 * STAGE;
// epilogue staging needs 128*192*4 = 98304 > 71680; take max explicitly:
static constexpr int GEMM_SMEM = 98304;

__global__ __launch_bounds__(512, 1) void qkv_gemm_wmma(const float* __restrict__ x)
{
    extern __shared__ char smem[];
    const int tid = threadIdx.x;
    const int wid = tid >> 5;
    const int warp_m = wid >> 2;
    const int warp_n = wid & 3;
    const int rowBase = blockIdx.x * 128;

    // x: 128 rows x 8 float4 = 1024 -> 2/thread
    const int xr_r[2] = { (tid + 0) >> 3, (tid + 512) >> 3 };
    const int xr_c[2] = { (tid + 0) & 7,  (tid + 512) & 7 };
    // W fp16 hi+lo: 2 x 768 uint4 = 1536 -> 3/thread
    int wb_r[3], wb_u[3];
    const __half* wb_src[3];
    int wb_dst[3];
#pragma unroll
    for (int t = 0; t < 3; t++) {
        int f = tid + t * 512;
        int g = (f < 768) ? f : (f - 768);
        wb_r[t] = g / 24;
        wb_u[t] = g - wb_r[t] * 24;
        wb_src[t] = (f < 768) ? g_Whi : g_Wlo;
        wb_dst[t] = (f < 768) ? OFF_BHI : OFF_BLO;
    }

    wmma::fragment<wmma::accumulator, 16, 16, 16, float> acc[2][3];
#pragma unroll
    for (int i = 0; i < 2; i++)
#pragma unroll
        for (int j = 0; j < 3; j++) wmma::fill_fragment(acc[i][j], 0.0f);

    // ---- prologue: chunk 0 into stage 0 ----
    {
        char* st = smem;
#pragma unroll
        for (int t = 0; t < 2; t++) {
            float4 v = *(const float4*)(x + (size_t)(rowBase + xr_r[t]) * C + xr_c[t] * 4);
            cvt_store4_h(st + OFF_A, xr_r[t] * A_LD + xr_c[t] * 4, v);
        }
#pragma unroll
        for (int t = 0; t < 3; t++) {
            *(uint4*)(st + wb_dst[t] + (wb_r[t] * B_LD + wb_u[t] * 8) * 2) =
                *(const uint4*)(wb_src[t] + (size_t)wb_r[t] * 192 + wb_u[t] * 8);
        }
    }
    __syncthreads();

    for (int c = 0; c < 12; c++) {
        char* st  = smem + (c & 1) * STAGE;
        char* nst = smem + ((c + 1) & 1) * STAGE;
        const int k1 = (c + 1) * 32;
        const bool more = (c + 1 < 12);

        float4 xr[2];
        uint4 wr[3];
        if (more) {
#pragma unroll
            for (int t = 0; t < 2; t++)
                xr[t] = *(const float4*)(x + (size_t)(rowBase + xr_r[t]) * C + k1 + xr_c[t] * 4);
#pragma unroll
            for (int t = 0; t < 3; t++)
                wr[t] = *(const uint4*)(wb_src[t] + (size_t)(k1 + wb_r[t]) * 192 + wb_u[t] * 8);
        }

        const __half* A   = (const __half*)(st + OFF_A);
        const __half* Bhi = (const __half*)(st + OFF_BHI);
        const __half* Blo = (const __half*)(st + OFF_BLO);
#pragma unroll
        for (int ks = 0; ks < 2; ks++) {
            wmma::fragment<wmma::matrix_a, 16, 16, 16, __half, wmma::row_major> af[2];
#pragma unroll
            for (int i = 0; i < 2; i++)
                wmma::load_matrix_sync(af[i], A + (warp_m * 32 + i * 16) * A_LD + ks * 16, A_LD);
#pragma unroll
            for (int j = 0; j < 3; j++) {
                int col = warp_n * 48 + j * 16;
                wmma::fragment<wmma::matrix_b, 16, 16, 16, __half, wmma::row_major> bh, bl;
                wmma::load_matrix_sync(bh, Bhi + ks * 16 * B_LD + col, B_LD);
                wmma::load_matrix_sync(bl, Blo + ks * 16 * B_LD + col, B_LD);
#pragma unroll
                for (int i = 0; i < 2; i++) {
                    wmma::mma_sync(acc[i][j], af[i], bh, acc[i][j]);
                    wmma::mma_sync(acc[i][j], af[i], bl, acc[i][j]);
                }
            }
        }

        if (more) {
#pragma unroll
            for (int t = 0; t < 2; t++)
                cvt_store4_h(nst + OFF_A, xr_r[t] * A_LD + xr_c[t] * 4, xr[t]);
#pragma unroll
            for (int t = 0; t < 3; t++)
                *(uint4*)(nst + wb_dst[t] + (wb_r[t] * B_LD + wb_u[t] * 8) * 2) = wr[t];
        }
        __syncthreads();
    }

    // ---- epilogue: stage fp32 in smem (2 passes of 64 rows), write fp16 -------
    float* Sb = (float*)smem;
    for (int p = 0; p < 2; p++) {
        __syncthreads();
        if ((warp_m >> 1) == p) {
#pragma unroll
            for (int i = 0; i < 2; i++)
#pragma unroll
                for (int j = 0; j < 3; j++)
                    wmma::store_matrix_sync(
                        Sb + ((warp_m & 1) * 32 + i * 16) * 192 + warp_n * 48 + j * 16,
                        acc[i][j], 192, wmma::mem_row_major);
        }
        __syncthreads();
#pragma unroll
        for (int t = 0; t < 12; t++) {
            int f = tid + t * 512;       // 0..6143 element pairs
            int r = f / 96;
            int pc = f - r * 96;
            int cc = pc * 2;             // even col 0..190
            float2 v = *(const float2*)(Sb + r * 192 + cc);
            int col = cc & 63;
            size_t off = (size_t)(rowBase + p * 64 + r) * HS + col;
            if (cc < 64) {
                __half2 hp = __floats2half2_rn(v.x, v.y);
                *(__half2*)(g_Qf + off) = hp;
            } else {
                __half* dhi = (cc < 128) ? g_Khi : g_Vhi;
                __half* dlo = (cc < 128) ? g_Klo : g_Vlo;
                __half h0 = __float2half(v.x);
                __half h1 = __float2half(v.y);
                __half2 hp; hp.x = h0; hp.y = h1;
                __half2 lp;
                lp.x = __float2half(v.x - __half2float(h0));
                lp.y = __float2half(v.y - __half2float(h1));
                *(__half2*)(dhi + off) = hp;
                *(__half2*)(dlo + off) = lp;
            }
        }
    }
}

// ---------------- attention: WMMA flash-style, fp16 2-product ------------------
// S = Qf (single) x (Khi+Klo)^T;  O += Pf (single) x (Vhi+Vlo)
static constexpr int LDH = 72;
static constexpr int AOF_QF  = 0;              // 128*72*2 = 18432
static constexpr int AOF_KHI = 18432;          // 64*72*2 = 9216
static constexpr int AOF_KLO = 27648;
static constexpr int AOF_VHI = 36864;
static constexpr int AOF_VLO = 46080;
static constexpr int AOF_S   = 55296;          // 128*72*4 = 36864
static constexpr int AOF_PF  = 92160;          // 128*72*2 = 18432
static constexpr int AOF_L   = 110592;         // 128*4
static constexpr int ATTN_SMEM = 111104;

__global__ __launch_bounds__(512, 1) void attn_wmma(float* __restrict__ out)
{
    extern __shared__ char smem[];
    __half* Qf  = (__half*)(smem + AOF_QF);
    __half* Khi = (__half*)(smem + AOF_KHI);
    __half* Klo = (__half*)(smem + AOF_KLO);
    __half* Vhi = (__half*)(smem + AOF_VHI);
    __half* Vlo = (__half*)(smem + AOF_VLO);
    float*  S   = (float*)(smem + AOF_S);
    __half* Pf  = (__half*)(smem + AOF_PF);
    float*  lbuf = (float*)(smem + AOF_L);

    const int qt  = blockIdx.x;
    const int b   = blockIdx.y;
    const int i0  = qt * 128;
    const int tid = threadIdx.x;
    const int wid = tid >> 5;
    const int rt  = wid >> 1;          // warp row-tile 0..7 (16 rows)
    const int cp  = wid & 1;           // warp col-pair

    if (tid < 128) lbuf[tid] = 0.0f;

    // load Q tile [128 x 64] fp16: 1024 uint4, 2/thread
    {
        const uint4* Qg = (const uint4*)(g_Qf + ((size_t)b * T + i0) * HS);
#pragma unroll
        for (int t = 0; t < 2; t++) {
            int f = tid + t * 512;
            int r = f >> 3, c8 = f & 7;
            *(uint4*)(Qf + r * LDH + c8 * 8) = Qg[f];
        }
    }
    __syncthreads();

    wmma::fragment<wmma::accumulator, 16, 16, 16, float> oacc[2];
    wmma::fill_fragment(oacc[0], 0.0f);
    wmma::fill_fragment(oacc[1], 0.0f);

    const float log2e_scale = 1.4426950408889634f * 0.125f;
    const int nkt = qt == 0 ? 2 : 4;
    const int i_glob = i0 + (tid >> 2);
    const int r_exp  = tid >> 2;
    const int cg     = tid & 3;

    for (int kt = 0; kt < nkt; kt++) {
        const int j0 = kt * 64;

        // load K,V tiles hi+lo: 4 x 512 uint4 = 2048, 4/thread
        {
            const uint4* srcs[4] = {
                (const uint4*)(g_Khi + ((size_t)b * T + j0) * HS),
                (const uint4*)(g_Klo + ((size_t)b * T + j0) * HS),
                (const uint4*)(g_Vhi + ((size_t)b * T + j0) * HS),
                (const uint4*)(g_Vlo + ((size_t)b * T + j0) * HS)
            };
            __half* dsts[4] = { Khi, Klo, Vhi, Vlo };
#pragma unroll
            for (int t = 0; t < 4; t++) {
                int f = tid + t * 512;
                int sel = f >> 9;
                int g = f & 511;
                int r = g >> 3, c8 = g & 7;
                *(uint4*)(dsts[sel] + r * LDH + c8 * 8) = srcs[sel][g];
            }
        }
        __syncthreads();

        // ---- S = Qf K^T ----
#pragma unroll
        for (int f = 0; f < 2; f++) {
            const int n = cp * 32 + f * 16;
            wmma::fragment<wmma::accumulator, 16, 16, 16, float> sacc;
            wmma::fill_fragment(sacc, 0.0f);
#pragma unroll
            for (int ks = 0; ks < 4; ks++) {
                wmma::fragment<wmma::matrix_a, 16, 16, 16, __half, wmma::row_major> aq;
                wmma::fragment<wmma::matrix_b, 16, 16, 16, __half, wmma::col_major> bh, bl;
                wmma::load_matrix_sync(aq, Qf + rt * 16 * LDH + ks * 16, LDH);
                wmma::load_matrix_sync(bh, Khi + n * LDH + ks * 16, LDH);
                wmma::load_matrix_sync(bl, Klo + n * LDH + ks * 16, LDH);
                wmma::mma_sync(sacc, aq, bh, sacc);
                wmma::mma_sync(sacc, aq, bl, sacc);
            }
            wmma::store_matrix_sync(S + rt * 16 * LDH + n, sacc, LDH,
                                    wmma::mem_row_major);
        }
        __syncthreads();

        // ---- exp + causal mask + row sums + Pf fp16 ----
        {
            float* srow = S + r_exp * LDH + cg * 16;
            __half* prow = Pf + r_exp * LDH + cg * 16;
            float ps = 0.0f;
#pragma unroll
            for (int c = 0; c < 16; c++) {
                int j = j0 + cg * 16 + c;
                float p = (j <= i_glob) ? exp2f(srow[c] * log2e_scale) : 0.0f;
                ps += p;
                prow[c] = __float2half(p);
            }
            ps += __shfl_xor_sync(0xFFFFFFFFu, ps, 1);
            ps += __shfl_xor_sync(0xFFFFFFFFu, ps, 2);
            if (cg == 0) lbuf[r_exp] += ps;
        }
        __syncthreads();

        // ---- O += Pf V ----
#pragma unroll
        for (int ks = 0; ks < 4; ks++) {
            wmma::fragment<wmma::matrix_a, 16, 16, 16, __half, wmma::row_major> ap;
            wmma::load_matrix_sync(ap, Pf + rt * 16 * LDH + ks * 16, LDH);
#pragma unroll
            for (int f = 0; f < 2; f++) {
                const int n = cp * 32 + f * 16;
                wmma::fragment<wmma::matrix_b, 16, 16, 16, __half, wmma::row_major> bh, bl;
                wmma::load_matrix_sync(bh, Vhi + ks * 16 * LDH + n, LDH);
                wmma::load_matrix_sync(bl, Vlo + ks * 16 * LDH + n, LDH);
                wmma::mma_sync(oacc[f], ap, bh, oacc[f]);
                wmma::mma_sync(oacc[f], ap, bl, oacc[f]);
            }
        }
        __syncthreads();
    }

    // ---- epilogue: normalize + write ----
#pragma unroll
    for (int f = 0; f < 2; f++) {
        const int n = cp * 32 + f * 16;
        wmma::store_matrix_sync(S + rt * 16 * LDH + n, oacc[f], LDH,
                                wmma::mem_row_major);
    }
    __syncthreads();
    {
        const float inv = 1.0f / lbuf[r_exp];
        const float* srow = S + r_exp * LDH + cg * 16;
        float* og = out + ((size_t)b * T + i0 + r_exp) * HS + cg * 16;
#pragma unroll
        for (int c4 = 0; c4 < 4; c4++) {
            float4 v = *(const float4*)(srow + c4 * 4);
            *(float4*)(og + c4 * 4) =
                make_float4(v.x * inv, v.y * inv, v.z * inv, v.w * inv);
        }
    }
}

// ---------------- launch --------------------------------------------------------
extern "C" void kernel_launch(void* const* d_in, const int* in_sizes, int n_in,
                              void* d_out, int out_size)
{
    (void)in_sizes; (void)n_in; (void)out_size;
    const float* x  = (const float*)d_in[0];
    const float* Wq = (const float*)d_in[1];
    const float* Wk = (const float*)d_in[2];
    const float* Wv = (const float*)d_in[3];
    float* out = (float*)d_out;

    convert_w<<<C, 192>>>(Wq, Wk, Wv);

    cudaFuncSetAttribute(qkv_gemm_wmma, cudaFuncAttributeMaxDynamicSharedMemorySize,
                         GEMM_SMEM);
    qkv_gemm_wmma<<<BT / 128, 512, GEMM_SMEM>>>(x);

    cudaFuncSetAttribute(attn_wmma, cudaFuncAttributeMaxDynamicSharedMemorySize,
                         ATTN_SMEM);
    dim3 agrid(2, B);
    attn_wmma<<<agrid, 512, ATTN_SMEM>>>(out);
}

// round 12
// speedup vs baseline: 1.8230x; 1.0961x over previous
#include <cuda_runtime.h>
#include <cuda_fp16.h>
#include <mma.h>
#include <cstdint>

using namespace nvcuda;

#define B 512
#define T 256
#define C 384
#define HS 64
#define BT (B * T)

// ---------------- scratch -----------------------------------------------------
__device__ __half g_Qf [BT * HS];          // Q single fp16
__device__ __half g_Khi[BT * HS];          // K split fp16
__device__ __half g_Klo[BT * HS];
__device__ __half g_Vhi[BT * HS];          // V split fp16
__device__ __half g_Vlo[BT * HS];
// fp16 split weights, [k][n] row-major, n in [0,192) = [Wq|Wk|Wv] columns
__device__ __half g_Whi[C * 192];
__device__ __half g_Wlo[C * 192];

// ---------------- W fp16 split kernel ------------------------------------------
__global__ void convert_w(const float* __restrict__ Wq,
                          const float* __restrict__ Wk,
                          const float* __restrict__ Wv)
{
    int k = blockIdx.x;     // 0..383
    int n = threadIdx.x;    // 0..191
    const float* W = (n < 64) ? Wq : ((n < 128) ? Wk : Wv);
    float w = W[(size_t)k * HS + (n & 63)];
    __half hi = __float2half(w);
    g_Whi[(size_t)k * 192 + n] = hi;
    g_Wlo[(size_t)k * 192 + n] = __float2half(w - __half2float(hi));
}

// convert float4 -> 4 single fp16, store 8 bytes
__device__ __forceinline__ void cvt_store4_h(char* base, int elemOff, float4 v)
{
    __half2 h01 = __floats2half2_rn(v.x, v.y);
    __half2 h23 = __floats2half2_rn(v.z, v.w);
    uint2 u;
    u.x = *(uint32_t*)&h01;
    u.y = *(uint32_t*)&h23;
    *(uint2*)((__half*)base + elemOff) = u;
}

// ---------------- QKV GEMM: WMMA fp16 2-product (x single, W split) -----------
// (unchanged from round 11)
static constexpr int A_LD = 40;
static constexpr int B_LD = 200;
static constexpr int OFF_A   = 0;
static constexpr int OFF_BHI = 10240;
static constexpr int OFF_BLO = 23040;
static constexpr int STAGE   = 35840;
static constexpr int GEMM_SMEM = 98304;   // epilogue staging 128*192*4 dominates

__global__ __launch_bounds__(512, 1) void qkv_gemm_wmma(const float* __restrict__ x)
{
    extern __shared__ char smem[];
    const int tid = threadIdx.x;
    const int wid = tid >> 5;
    const int warp_m = wid >> 2;
    const int warp_n = wid & 3;
    const int rowBase = blockIdx.x * 128;

    const int xr_r[2] = { (tid + 0) >> 3, (tid + 512) >> 3 };
    const int xr_c[2] = { (tid + 0) & 7,  (tid + 512) & 7 };
    int wb_r[3], wb_u[3];
    const __half* wb_src[3];
    int wb_dst[3];
#pragma unroll
    for (int t = 0; t < 3; t++) {
        int f = tid + t * 512;
        int g = (f < 768) ? f : (f - 768);
        wb_r[t] = g / 24;
        wb_u[t] = g - wb_r[t] * 24;
        wb_src[t] = (f < 768) ? g_Whi : g_Wlo;
        wb_dst[t] = (f < 768) ? OFF_BHI : OFF_BLO;
    }

    wmma::fragment<wmma::accumulator, 16, 16, 16, float> acc[2][3];
#pragma unroll
    for (int i = 0; i < 2; i++)
#pragma unroll
        for (int j = 0; j < 3; j++) wmma::fill_fragment(acc[i][j], 0.0f);

    {
        char* st = smem;
#pragma unroll
        for (int t = 0; t < 2; t++) {
            float4 v = *(const float4*)(x + (size_t)(rowBase + xr_r[t]) * C + xr_c[t] * 4);
            cvt_store4_h(st + OFF_A, xr_r[t] * A_LD + xr_c[t] * 4, v);
        }
#pragma unroll
        for (int t = 0; t < 3; t++) {
            *(uint4*)(st + wb_dst[t] + (wb_r[t] * B_LD + wb_u[t] * 8) * 2) =
                *(const uint4*)(wb_src[t] + (size_t)wb_r[t] * 192 + wb_u[t] * 8);
        }
    }
    __syncthreads();

    for (int c = 0; c < 12; c++) {
        char* st  = smem + (c & 1) * STAGE;
        char* nst = smem + ((c + 1) & 1) * STAGE;
        const int k1 = (c + 1) * 32;
        const bool more = (c + 1 < 12);

        float4 xr[2];
        uint4 wr[3];
        if (more) {
#pragma unroll
            for (int t = 0; t < 2; t++)
                xr[t] = *(const float4*)(x + (size_t)(rowBase + xr_r[t]) * C + k1 + xr_c[t] * 4);
#pragma unroll
            for (int t = 0; t < 3; t++)
                wr[t] = *(const uint4*)(wb_src[t] + (size_t)(k1 + wb_r[t]) * 192 + wb_u[t] * 8);
        }

        const __half* A   = (const __half*)(st + OFF_A);
        const __half* Bhi = (const __half*)(st + OFF_BHI);
        const __half* Blo = (const __half*)(st + OFF_BLO);
#pragma unroll
        for (int ks = 0; ks < 2; ks++) {
            wmma::fragment<wmma::matrix_a, 16, 16, 16, __half, wmma::row_major> af[2];
#pragma unroll
            for (int i = 0; i < 2; i++)
                wmma::load_matrix_sync(af[i], A + (warp_m * 32 + i * 16) * A_LD + ks * 16, A_LD);
#pragma unroll
            for (int j = 0; j < 3; j++) {
                int col = warp_n * 48 + j * 16;
                wmma::fragment<wmma::matrix_b, 16, 16, 16, __half, wmma::row_major> bh, bl;
                wmma::load_matrix_sync(bh, Bhi + ks * 16 * B_LD + col, B_LD);
                wmma::load_matrix_sync(bl, Blo + ks * 16 * B_LD + col, B_LD);
#pragma unroll
                for (int i = 0; i < 2; i++) {
                    wmma::mma_sync(acc[i][j], af[i], bh, acc[i][j]);
                    wmma::mma_sync(acc[i][j], af[i], bl, acc[i][j]);
                }
            }
        }

        if (more) {
#pragma unroll
            for (int t = 0; t < 2; t++)
                cvt_store4_h(nst + OFF_A, xr_r[t] * A_LD + xr_c[t] * 4, xr[t]);
#pragma unroll
            for (int t = 0; t < 3; t++)
                *(uint4*)(nst + wb_dst[t] + (wb_r[t] * B_LD + wb_u[t] * 8) * 2) = wr[t];
        }
        __syncthreads();
    }

    // ---- epilogue: stage fp32 in smem (2 passes of 64 rows), write fp16 -------
    float* Sb = (float*)smem;
    for (int p = 0; p < 2; p++) {
        __syncthreads();
        if ((warp_m >> 1) == p) {
#pragma unroll
            for (int i = 0; i < 2; i++)
#pragma unroll
                for (int j = 0; j < 3; j++)
                    wmma::store_matrix_sync(
                        Sb + ((warp_m & 1) * 32 + i * 16) * 192 + warp_n * 48 + j * 16,
                        acc[i][j], 192, wmma::mem_row_major);
        }
        __syncthreads();
#pragma unroll
        for (int t = 0; t < 12; t++) {
            int f = tid + t * 512;
            int r = f / 96;
            int pc = f - r * 96;
            int cc = pc * 2;
            float2 v = *(const float2*)(Sb + r * 192 + cc);
            int col = cc & 63;
            size_t off = (size_t)(rowBase + p * 64 + r) * HS + col;
            if (cc < 64) {
                __half2 hp = __floats2half2_rn(v.x, v.y);
                *(__half2*)(g_Qf + off) = hp;
            } else {
                __half* dhi = (cc < 128) ? g_Khi : g_Vhi;
                __half* dlo = (cc < 128) ? g_Klo : g_Vlo;
                __half h0 = __float2half(v.x);
                __half h1 = __float2half(v.y);
                __half2 hp; hp.x = h0; hp.y = h1;
                __half2 lp;
                lp.x = __float2half(v.x - __half2float(h0));
                lp.y = __float2half(v.y - __half2float(h1));
                *(__half2*)(dhi + off) = hp;
                *(__half2*)(dlo + off) = lp;
            }
        }
    }
}

// ---------------- attention v7: 64x64 tiles, 2 CTAs/SM -------------------------
// Grid (4, 512): q-tile 64 rows; nkt = qt+1 key tiles (exact causal coverage).
// 512 threads = 16 warps (4x4); warp tile 16x16 for both S and O.
static constexpr int LDH = 72;
static constexpr int AOF_QF  = 0;              // 64*72*2 = 9216
static constexpr int AOF_KHI = 9216;
static constexpr int AOF_KLO = 18432;
static constexpr int AOF_VHI = 27648;
static constexpr int AOF_VLO = 36864;
static constexpr int AOF_S   = 46080;          // 64*72*4 = 18432
static constexpr int AOF_PF  = 64512;          // 9216
static constexpr int AOF_L   = 73728;          // 256
static constexpr int ATTN_SMEM = 73984;

__global__ __launch_bounds__(512, 2) void attn_wmma(float* __restrict__ out)
{
    extern __shared__ char smem[];
    __half* Qf  = (__half*)(smem + AOF_QF);
    __half* Khi = (__half*)(smem + AOF_KHI);
    __half* Klo = (__half*)(smem + AOF_KLO);
    __half* Vhi = (__half*)(smem + AOF_VHI);
    __half* Vlo = (__half*)(smem + AOF_VLO);
    float*  S   = (float*)(smem + AOF_S);
    __half* Pf  = (__half*)(smem + AOF_PF);
    float*  lbuf = (float*)(smem + AOF_L);

    const int qt  = blockIdx.x;        // 0..3
    const int b   = blockIdx.y;        // 0..511
    const int i0  = qt * 64;
    const int tid = threadIdx.x;
    const int wid = tid >> 5;
    const int rt  = wid >> 2;          // warp row-tile 0..3 (16 rows)
    const int ct  = wid & 3;           // warp col-tile 0..3 (16 cols)

    if (tid < 64) lbuf[tid] = 0.0f;

    // load Q tile [64 x 64] fp16: 512 uint4, 1/thread
    {
        const uint4* Qg = (const uint4*)(g_Qf + ((size_t)b * T + i0) * HS);
        int r = tid >> 3, c8 = tid & 7;
        *(uint4*)(Qf + r * LDH + c8 * 8) = Qg[tid];
    }
    __syncthreads();

    wmma::fragment<wmma::accumulator, 16, 16, 16, float> oacc;
    wmma::fill_fragment(oacc, 0.0f);

    const float log2e_scale = 1.4426950408889634f * 0.125f;
    const int nkt = qt + 1;
    const int r_exp  = tid >> 3;           // 0..63
    const int cg     = tid & 7;            // col group of 8
    const int i_glob = i0 + r_exp;

    for (int kt = 0; kt < nkt; kt++) {
        const int j0 = kt * 64;

        // load K,V tiles hi+lo: 4 x 512 uint4, 4/thread
        {
            const uint4* srcs[4] = {
                (const uint4*)(g_Khi + ((size_t)b * T + j0) * HS),
                (const uint4*)(g_Klo + ((size_t)b * T + j0) * HS),
                (const uint4*)(g_Vhi + ((size_t)b * T + j0) * HS),
                (const uint4*)(g_Vlo + ((size_t)b * T + j0) * HS)
            };
            __half* dsts[4] = { Khi, Klo, Vhi, Vlo };
#pragma unroll
            for (int t = 0; t < 4; t++) {
                int f = tid + t * 512;
                int sel = f >> 9;           // == t (constant per unrolled iter)
                int g = f & 511;
                int r = g >> 3, c8 = g & 7;
                *(uint4*)(dsts[sel] + r * LDH + c8 * 8) = srcs[sel][g];
            }
        }
        __syncthreads();

        // ---- S = Qf K^T : warp tile 16x16 ----
        {
            const int n = ct * 16;
            wmma::fragment<wmma::accumulator, 16, 16, 16, float> sacc;
            wmma::fill_fragment(sacc, 0.0f);
#pragma unroll
            for (int ks = 0; ks < 4; ks++) {
                wmma::fragment<wmma::matrix_a, 16, 16, 16, __half, wmma::row_major> aq;
                wmma::fragment<wmma::matrix_b, 16, 16, 16, __half, wmma::col_major> bh, bl;
                wmma::load_matrix_sync(aq, Qf + rt * 16 * LDH + ks * 16, LDH);
                wmma::load_matrix_sync(bh, Khi + n * LDH + ks * 16, LDH);
                wmma::load_matrix_sync(bl, Klo + n * LDH + ks * 16, LDH);
                wmma::mma_sync(sacc, aq, bh, sacc);
                wmma::mma_sync(sacc, aq, bl, sacc);
            }
            wmma::store_matrix_sync(S + rt * 16 * LDH + n, sacc, LDH,
                                    wmma::mem_row_major);
        }
        __syncthreads();

        // ---- exp + causal mask + row sums + Pf fp16 (8 elems/thread) ----
        {
            const float* srow = S + r_exp * LDH + cg * 8;
            float ps = 0.0f;
            float p[8];
#pragma unroll
            for (int c = 0; c < 8; c++) {
                int j = j0 + cg * 8 + c;
                p[c] = (j <= i_glob) ? exp2f(srow[c] * log2e_scale) : 0.0f;
                ps += p[c];
            }
            // pack 8 halves -> uint4, single 16B store
            __half2 h0 = __floats2half2_rn(p[0], p[1]);
            __half2 h1 = __floats2half2_rn(p[2], p[3]);
            __half2 h2 = __floats2half2_rn(p[4], p[5]);
            __half2 h3 = __floats2half2_rn(p[6], p[7]);
            uint4 u;
            u.x = *(uint32_t*)&h0; u.y = *(uint32_t*)&h1;
            u.z = *(uint32_t*)&h2; u.w = *(uint32_t*)&h3;
            *(uint4*)(Pf + r_exp * LDH + cg * 8) = u;
            // reduce across the 8 lanes owning this row
            ps += __shfl_xor_sync(0xFFFFFFFFu, ps, 1);
            ps += __shfl_xor_sync(0xFFFFFFFFu, ps, 2);
            ps += __shfl_xor_sync(0xFFFFFFFFu, ps, 4);
            if (cg == 0) lbuf[r_exp] += ps;
        }
        __syncthreads();

        // ---- O += Pf V : warp tile 16x16 ----
        {
            const int n = ct * 16;
#pragma unroll
            for (int ks = 0; ks < 4; ks++) {
                wmma::fragment<wmma::matrix_a, 16, 16, 16, __half, wmma::row_major> ap;
                wmma::fragment<wmma::matrix_b, 16, 16, 16, __half, wmma::row_major> bh, bl;
                wmma::load_matrix_sync(ap, Pf + rt * 16 * LDH + ks * 16, LDH);
                wmma::load_matrix_sync(bh, Vhi + ks * 16 * LDH + n, LDH);
                wmma::load_matrix_sync(bl, Vlo + ks * 16 * LDH + n, LDH);
                wmma::mma_sync(oacc, ap, bh, oacc);
                wmma::mma_sync(oacc, ap, bl, oacc);
            }
        }
        __syncthreads();
    }

    // ---- epilogue: normalize + write ----
    wmma::store_matrix_sync(S + rt * 16 * LDH + ct * 16, oacc, LDH,
                            wmma::mem_row_major);
    __syncthreads();
    {
        const float inv = 1.0f / lbuf[r_exp];
        const float* srow = S + r_exp * LDH + cg * 8;
        float* og = out + ((size_t)b * T + i0 + r_exp) * HS + cg * 8;
        float4 v0 = *(const float4*)(srow);
        float4 v1 = *(const float4*)(srow + 4);
        *(float4*)(og)     = make_float4(v0.x * inv, v0.y * inv, v0.z * inv, v0.w * inv);
        *(float4*)(og + 4) = make_float4(v1.x * inv, v1.y * inv, v1.z * inv, v1.w * inv);
    }
}

// ---------------- launch --------------------------------------------------------
extern "C" void kernel_launch(void* const* d_in, const int* in_sizes, int n_in,
                              void* d_out, int out_size)
{
    (void)in_sizes; (void)n_in; (void)out_size;
    const float* x  = (const float*)d_in[0];
    const float* Wq = (const float*)d_in[1];
    const float* Wk = (const float*)d_in[2];
    const float* Wv = (const float*)d_in[3];
    float* out = (float*)d_out;

    convert_w<<<C, 192>>>(Wq, Wk, Wv);

    cudaFuncSetAttribute(qkv_gemm_wmma, cudaFuncAttributeMaxDynamicSharedMemorySize,
                         GEMM_SMEM);
    qkv_gemm_wmma<<<BT / 128, 512, GEMM_SMEM>>>(x);

    cudaFuncSetAttribute(attn_wmma, cudaFuncAttributeMaxDynamicSharedMemorySize,
                         ATTN_SMEM);
    dim3 agrid(4, B);
    attn_wmma<<<agrid, 512, ATTN_SMEM>>>(out);
}

// round 13
// speedup vs baseline: 1.9998x; 1.0970x over previous
#include <cuda_runtime.h>
#include <cuda_fp16.h>
#include <mma.h>
#include <cstdint>

using namespace nvcuda;

#define B 512
#define T 256
#define C 384
#define HS 64
#define BT (B * T)

// ---------------- scratch -----------------------------------------------------
__device__ __half g_Qf [BT * HS];          // Q single fp16
__device__ __half g_Khi[BT * HS];          // K split fp16
__device__ __half g_Klo[BT * HS];
__device__ __half g_Vhi[BT * HS];          // V split fp16
__device__ __half g_Vlo[BT * HS];
// fp16 single weights, [k][n] row-major, n in [0,192) = [Wq|Wk|Wv] columns
__device__ __half g_Wh[C * 192];

// ---------------- W fp16 kernel -------------------------------------------------
__global__ void convert_w(const float* __restrict__ Wq,
                          const float* __restrict__ Wk,
                          const float* __restrict__ Wv)
{
    int k = blockIdx.x;     // 0..383
    int n = threadIdx.x;    // 0..191
    const float* W = (n < 64) ? Wq : ((n < 128) ? Wk : Wv);
    g_Wh[(size_t)k * 192 + n] = __float2half(W[(size_t)k * HS + (n & 63)]);
}

// convert float4 -> 4 single fp16, store 8 bytes
__device__ __forceinline__ void cvt_store4_h(char* base, int elemOff, float4 v)
{
    __half2 h01 = __floats2half2_rn(v.x, v.y);
    __half2 h23 = __floats2half2_rn(v.z, v.w);
    uint2 u;
    u.x = *(uint32_t*)&h01;
    u.y = *(uint32_t*)&h23;
    *(uint2*)((__half*)base + elemOff) = u;
}

// ---------------- QKV GEMM: WMMA pure fp16 (1 product), double-buffered --------
// 512 threads = 16 warps (4M x 4N). CTA tile 128x192, BK=32, 12 chunks.
static constexpr int A_LD = 40;
static constexpr int B_LD = 200;
static constexpr int OFF_A = 0;            // 128*40*2 = 10240
static constexpr int OFF_B = 10240;        // 32*200*2 = 12800
static constexpr int STAGE = 23040;
static constexpr int GEMM_SMEM = 49152;    // epilogue staging 64*192*4 dominates

__global__ __launch_bounds__(512, 1) void qkv_gemm_wmma(const float* __restrict__ x)
{
    extern __shared__ char smem[];
    const int tid = threadIdx.x;
    const int wid = tid >> 5;
    const int warp_m = wid >> 2;
    const int warp_n = wid & 3;
    const int rowBase = blockIdx.x * 128;

    // x: 128 rows x 8 float4 = 1024 -> 2/thread
    const int xr_r[2] = { (tid + 0) >> 3, (tid + 512) >> 3 };
    const int xr_c[2] = { (tid + 0) & 7,  (tid + 512) & 7 };
    // W fp16: 32 rows x 24 uint4 = 768 -> t0 all threads, t1 tid<256
    const bool wb_act1 = (tid < 256);
    const int wf0 = tid, wf1 = tid + 512;
    const int wb_r0 = wf0 / 24, wb_u0 = wf0 - wb_r0 * 24;
    const int wb_r1 = wf1 / 24, wb_u1 = wf1 - wb_r1 * 24;

    wmma::fragment<wmma::accumulator, 16, 16, 16, float> acc[2][3];
#pragma unroll
    for (int i = 0; i < 2; i++)
#pragma unroll
        for (int j = 0; j < 3; j++) wmma::fill_fragment(acc[i][j], 0.0f);

    // ---- prologue: chunk 0 into stage 0 ----
    {
        char* st = smem;
#pragma unroll
        for (int t = 0; t < 2; t++) {
            float4 v = *(const float4*)(x + (size_t)(rowBase + xr_r[t]) * C + xr_c[t] * 4);
            cvt_store4_h(st + OFF_A, xr_r[t] * A_LD + xr_c[t] * 4, v);
        }
        *(uint4*)(st + OFF_B + (wb_r0 * B_LD + wb_u0 * 8) * 2) =
            *(const uint4*)(g_Wh + (size_t)wb_r0 * 192 + wb_u0 * 8);
        if (wb_act1)
            *(uint4*)(st + OFF_B + (wb_r1 * B_LD + wb_u1 * 8) * 2) =
                *(const uint4*)(g_Wh + (size_t)wb_r1 * 192 + wb_u1 * 8);
    }
    __syncthreads();

    for (int c = 0; c < 12; c++) {
        char* st  = smem + (c & 1) * STAGE;
        char* nst = smem + ((c + 1) & 1) * STAGE;
        const int k1 = (c + 1) * 32;
        const bool more = (c + 1 < 12);

        // global prefetch of chunk c+1
        float4 xr[2];
        uint4 wr0, wr1;
        if (more) {
#pragma unroll
            for (int t = 0; t < 2; t++)
                xr[t] = *(const float4*)(x + (size_t)(rowBase + xr_r[t]) * C + k1 + xr_c[t] * 4);
            wr0 = *(const uint4*)(g_Wh + (size_t)(k1 + wb_r0) * 192 + wb_u0 * 8);
            if (wb_act1)
                wr1 = *(const uint4*)(g_Wh + (size_t)(k1 + wb_r1) * 192 + wb_u1 * 8);
        }

        // compute chunk c: 12 mma/warp
        const __half* A  = (const __half*)(st + OFF_A);
        const __half* Bs = (const __half*)(st + OFF_B);
#pragma unroll
        for (int ks = 0; ks < 2; ks++) {
            wmma::fragment<wmma::matrix_a, 16, 16, 16, __half, wmma::row_major> af[2];
#pragma unroll
            for (int i = 0; i < 2; i++)
                wmma::load_matrix_sync(af[i], A + (warp_m * 32 + i * 16) * A_LD + ks * 16, A_LD);
#pragma unroll
            for (int j = 0; j < 3; j++) {
                int col = warp_n * 48 + j * 16;
                wmma::fragment<wmma::matrix_b, 16, 16, 16, __half, wmma::row_major> bf;
                wmma::load_matrix_sync(bf, Bs + ks * 16 * B_LD + col, B_LD);
#pragma unroll
                for (int i = 0; i < 2; i++)
                    wmma::mma_sync(acc[i][j], af[i], bf, acc[i][j]);
            }
        }

        // store prefetched chunk into the other stage
        if (more) {
#pragma unroll
            for (int t = 0; t < 2; t++)
                cvt_store4_h(nst + OFF_A, xr_r[t] * A_LD + xr_c[t] * 4, xr[t]);
            *(uint4*)(nst + OFF_B + (wb_r0 * B_LD + wb_u0 * 8) * 2) = wr0;
            if (wb_act1)
                *(uint4*)(nst + OFF_B + (wb_r1 * B_LD + wb_u1 * 8) * 2) = wr1;
        }
        __syncthreads();
    }

    // ---- epilogue: stage fp32 in smem (2 passes of 64 rows), write fp16 -------
    float* Sb = (float*)smem;
    for (int p = 0; p < 2; p++) {
        __syncthreads();
        if ((warp_m >> 1) == p) {
#pragma unroll
            for (int i = 0; i < 2; i++)
#pragma unroll
                for (int j = 0; j < 3; j++)
                    wmma::store_matrix_sync(
                        Sb + ((warp_m & 1) * 32 + i * 16) * 192 + warp_n * 48 + j * 16,
                        acc[i][j], 192, wmma::mem_row_major);
        }
        __syncthreads();
#pragma unroll
        for (int t = 0; t < 12; t++) {
            int f = tid + t * 512;       // 0..6143 element pairs
            int r = f / 96;
            int pc = f - r * 96;
            int cc = pc * 2;             // even col 0..190
            float2 v = *(const float2*)(Sb + r * 192 + cc);
            int col = cc & 63;
            size_t off = (size_t)(rowBase + p * 64 + r) * HS + col;
            if (cc < 64) {
                __half2 hp = __floats2half2_rn(v.x, v.y);
                *(__half2*)(g_Qf + off) = hp;
            } else {
                __half* dhi = (cc < 128) ? g_Khi : g_Vhi;
                __half* dlo = (cc < 128) ? g_Klo : g_Vlo;
                __half h0 = __float2half(v.x);
                __half h1 = __float2half(v.y);
                __half2 hp; hp.x = h0; hp.y = h1;
                __half2 lp;
                lp.x = __float2half(v.x - __half2float(h0));
                lp.y = __float2half(v.y - __half2float(h1));
                *(__half2*)(dhi + off) = hp;
                *(__half2*)(dlo + off) = lp;
            }
        }
    }
}

// ---------------- attention v7: 64x64 tiles, 2 CTAs/SM (unchanged) ------------
static constexpr int LDH = 72;
static constexpr int AOF_QF  = 0;              // 64*72*2 = 9216
static constexpr int AOF_KHI = 9216;
static constexpr int AOF_KLO = 18432;
static constexpr int AOF_VHI = 27648;
static constexpr int AOF_VLO = 36864;
static constexpr int AOF_S   = 46080;          // 64*72*4 = 18432
static constexpr int AOF_PF  = 64512;          // 9216
static constexpr int AOF_L   = 73728;          // 256
static constexpr int ATTN_SMEM = 73984;

__global__ __launch_bounds__(512, 2) void attn_wmma(float* __restrict__ out)
{
    extern __shared__ char smem[];
    __half* Qf  = (__half*)(smem + AOF_QF);
    __half* Khi = (__half*)(smem + AOF_KHI);
    __half* Klo = (__half*)(smem + AOF_KLO);
    __half* Vhi = (__half*)(smem + AOF_VHI);
    __half* Vlo = (__half*)(smem + AOF_VLO);
    float*  S   = (float*)(smem + AOF_S);
    __half* Pf  = (__half*)(smem + AOF_PF);
    float*  lbuf = (float*)(smem + AOF_L);

    const int qt  = blockIdx.x;        // 0..3
    const int b   = blockIdx.y;        // 0..511
    const int i0  = qt * 64;
    const int tid = threadIdx.x;
    const int wid = tid >> 5;
    const int rt  = wid >> 2;          // warp row-tile 0..3
    const int ct  = wid & 3;           // warp col-tile 0..3

    if (tid < 64) lbuf[tid] = 0.0f;

    // load Q tile [64 x 64] fp16: 512 uint4, 1/thread
    {
        const uint4* Qg = (const uint4*)(g_Qf + ((size_t)b * T + i0) * HS);
        int r = tid >> 3, c8 = tid & 7;
        *(uint4*)(Qf + r * LDH + c8 * 8) = Qg[tid];
    }
    __syncthreads();

    wmma::fragment<wmma::accumulator, 16, 16, 16, float> oacc;
    wmma::fill_fragment(oacc, 0.0f);

    const float log2e_scale = 1.4426950408889634f * 0.125f;
    const int nkt = qt + 1;
    const int r_exp  = tid >> 3;
    const int cg     = tid & 7;
    const int i_glob = i0 + r_exp;

    for (int kt = 0; kt < nkt; kt++) {
        const int j0 = kt * 64;

        {
            const uint4* srcs[4] = {
                (const uint4*)(g_Khi + ((size_t)b * T + j0) * HS),
                (const uint4*)(g_Klo + ((size_t)b * T + j0) * HS),
                (const uint4*)(g_Vhi + ((size_t)b * T + j0) * HS),
                (const uint4*)(g_Vlo + ((size_t)b * T + j0) * HS)
            };
            __half* dsts[4] = { Khi, Klo, Vhi, Vlo };
#pragma unroll
            for (int t = 0; t < 4; t++) {
                int f = tid + t * 512;
                int sel = f >> 9;
                int g = f & 511;
                int r = g >> 3, c8 = g & 7;
                *(uint4*)(dsts[sel] + r * LDH + c8 * 8) = srcs[sel][g];
            }
        }
        __syncthreads();

        // ---- S = Qf K^T ----
        {
            const int n = ct * 16;
            wmma::fragment<wmma::accumulator, 16, 16, 16, float> sacc;
            wmma::fill_fragment(sacc, 0.0f);
#pragma unroll
            for (int ks = 0; ks < 4; ks++) {
                wmma::fragment<wmma::matrix_a, 16, 16, 16, __half, wmma::row_major> aq;
                wmma::fragment<wmma::matrix_b, 16, 16, 16, __half, wmma::col_major> bh, bl;
                wmma::load_matrix_sync(aq, Qf + rt * 16 * LDH + ks * 16, LDH);
                wmma::load_matrix_sync(bh, Khi + n * LDH + ks * 16, LDH);
                wmma::load_matrix_sync(bl, Klo + n * LDH + ks * 16, LDH);
                wmma::mma_sync(sacc, aq, bh, sacc);
                wmma::mma_sync(sacc, aq, bl, sacc);
            }
            wmma::store_matrix_sync(S + rt * 16 * LDH + n, sacc, LDH,
                                    wmma::mem_row_major);
        }
        __syncthreads();

        // ---- exp + causal mask + row sums + Pf fp16 ----
        {
            const float* srow = S + r_exp * LDH + cg * 8;
            float ps = 0.0f;
            float p[8];
#pragma unroll
            for (int c = 0; c < 8; c++) {
                int j = j0 + cg * 8 + c;
                p[c] = (j <= i_glob) ? exp2f(srow[c] * log2e_scale) : 0.0f;
                ps += p[c];
            }
            __half2 h0 = __floats2half2_rn(p[0], p[1]);
            __half2 h1 = __floats2half2_rn(p[2], p[3]);
            __half2 h2 = __floats2half2_rn(p[4], p[5]);
            __half2 h3 = __floats2half2_rn(p[6], p[7]);
            uint4 u;
            u.x = *(uint32_t*)&h0; u.y = *(uint32_t*)&h1;
            u.z = *(uint32_t*)&h2; u.w = *(uint32_t*)&h3;
            *(uint4*)(Pf + r_exp * LDH + cg * 8) = u;
            ps += __shfl_xor_sync(0xFFFFFFFFu, ps, 1);
            ps += __shfl_xor_sync(0xFFFFFFFFu, ps, 2);
            ps += __shfl_xor_sync(0xFFFFFFFFu, ps, 4);
            if (cg == 0) lbuf[r_exp] += ps;
        }
        __syncthreads();

        // ---- O += Pf V ----
        {
            const int n = ct * 16;
#pragma unroll
            for (int ks = 0; ks < 4; ks++) {
                wmma::fragment<wmma::matrix_a, 16, 16, 16, __half, wmma::row_major> ap;
                wmma::fragment<wmma::matrix_b, 16, 16, 16, __half, wmma::row_major> bh, bl;
                wmma::load_matrix_sync(ap, Pf + rt * 16 * LDH + ks * 16, LDH);
                wmma::load_matrix_sync(bh, Vhi + ks * 16 * LDH + n, LDH);
                wmma::load_matrix_sync(bl, Vlo + ks * 16 * LDH + n, LDH);
                wmma::mma_sync(oacc, ap, bh, oacc);
                wmma::mma_sync(oacc, ap, bl, oacc);
            }
        }
        __syncthreads();
    }

    // ---- epilogue: normalize + write ----
    wmma::store_matrix_sync(S + rt * 16 * LDH + ct * 16, oacc, LDH,
                            wmma::mem_row_major);
    __syncthreads();
    {
        const float inv = 1.0f / lbuf[r_exp];
        const float* srow = S + r_exp * LDH + cg * 8;
        float* og = out + ((size_t)b * T + i0 + r_exp) * HS + cg * 8;
        float4 v0 = *(const float4*)(srow);
        float4 v1 = *(const float4*)(srow + 4);
        *(float4*)(og)     = make_float4(v0.x * inv, v0.y * inv, v0.z * inv, v0.w * inv);
        *(float4*)(og + 4) = make_float4(v1.x * inv, v1.y * inv, v1.z * inv, v1.w * inv);
    }
}

// ---------------- launch --------------------------------------------------------
extern "C" void kernel_launch(void* const* d_in, const int* in_sizes, int n_in,
                              void* d_out, int out_size)
{
    (void)in_sizes; (void)n_in; (void)out_size;
    const float* x  = (const float*)d_in[0];
    const float* Wq = (const float*)d_in[1];
    const float* Wk = (const float*)d_in[2];
    const float* Wv = (const float*)d_in[3];
    float* out = (float*)d_out;

    convert_w<<<C, 192>>>(Wq, Wk, Wv);

    cudaFuncSetAttribute(qkv_gemm_wmma, cudaFuncAttributeMaxDynamicSharedMemorySize,
                         GEMM_SMEM);
    qkv_gemm_wmma<<<BT / 128, 512, GEMM_SMEM>>>(x);

    cudaFuncSetAttribute(attn_wmma, cudaFuncAttributeMaxDynamicSharedMemorySize,
                         ATTN_SMEM);
    dim3 agrid(4, B);
    attn_wmma<<<agrid, 512, ATTN_SMEM>>>(out);
}

// round 14
// speedup vs baseline: 2.1027x; 1.0514x over previous
#include <cuda_runtime.h>
#include <cuda_fp16.h>
#include <mma.h>
#include <cstdint>

using namespace nvcuda;

#define B 512
#define T 256
#define C 384
#define HS 64
#define BT (B * T)

// ---------------- scratch -----------------------------------------------------
__device__ __half g_Qf [BT * HS];          // Q single fp16
__device__ __half g_Khi[BT * HS];          // K split fp16
__device__ __half g_Klo[BT * HS];
__device__ __half g_Vhi[BT * HS];          // V split fp16
__device__ __half g_Vlo[BT * HS];
// fp16 single weights, [k][n] row-major, n in [0,192) = [Wq|Wk|Wv] columns
__device__ __half g_Wh[C * 192];

// ---------------- W fp16 kernel -------------------------------------------------
__global__ void convert_w(const float* __restrict__ Wq,
                          const float* __restrict__ Wk,
                          const float* __restrict__ Wv)
{
    int k = blockIdx.x;     // 0..383
    int n = threadIdx.x;    // 0..191
    const float* W = (n < 64) ? Wq : ((n < 128) ? Wk : Wv);
    g_Wh[(size_t)k * 192 + n] = __float2half(W[(size_t)k * HS + (n & 63)]);
}

// convert float4 -> 4 single fp16, store 8 bytes
__device__ __forceinline__ void cvt_store4_h(char* base, int elemOff, float4 v)
{
    __half2 h01 = __floats2half2_rn(v.x, v.y);
    __half2 h23 = __floats2half2_rn(v.z, v.w);
    uint2 u;
    u.x = *(uint32_t*)&h01;
    u.y = *(uint32_t*)&h23;
    *(uint2*)((__half*)base + elemOff) = u;
}

// ---------------- QKV GEMM: WMMA pure fp16, tile 64x192, 2 CTAs/SM -------------
// 256 threads = 8 warps (2M x 4N), warp tile 32x48. BK=32, 12 chunks.
static constexpr int A_LD = 40;
static constexpr int B_LD = 200;
static constexpr int OFF_A = 0;            // 64*40*2 = 5120
static constexpr int OFF_B = 5120;         // 32*200*2 = 12800
static constexpr int STAGE = 17920;
static constexpr int GEMM_SMEM = 49152;    // epilogue staging 64*192*4 dominates

__global__ __launch_bounds__(256, 2) void qkv_gemm_wmma(const float* __restrict__ x)
{
    extern __shared__ char smem[];
    const int tid = threadIdx.x;
    const int wid = tid >> 5;
    const int warp_m = wid >> 2;       // 0..1 -> rows 32*warp_m
    const int warp_n = wid & 3;        // 0..3 -> cols 48*warp_n
    const int rowBase = blockIdx.x * 64;

    // x: 64 rows x 8 float4 = 512 -> 2/thread
    const int xr_r[2] = { (tid + 0) >> 3, (tid + 256) >> 3 };
    const int xr_c[2] = { (tid + 0) & 7,  (tid + 256) & 7 };
    // W fp16: 32 rows x 24 uint4 = 768 -> 3/thread
    int wb_r[3], wb_u[3];
#pragma unroll
    for (int t = 0; t < 3; t++) {
        int f = tid + t * 256;
        wb_r[t] = f / 24;
        wb_u[t] = f - wb_r[t] * 24;
    }

    wmma::fragment<wmma::accumulator, 16, 16, 16, float> acc[2][3];
#pragma unroll
    for (int i = 0; i < 2; i++)
#pragma unroll
        for (int j = 0; j < 3; j++) wmma::fill_fragment(acc[i][j], 0.0f);

    // ---- prologue: chunk 0 into stage 0 ----
    {
        char* st = smem;
#pragma unroll
        for (int t = 0; t < 2; t++) {
            float4 v = *(const float4*)(x + (size_t)(rowBase + xr_r[t]) * C + xr_c[t] * 4);
            cvt_store4_h(st + OFF_A, xr_r[t] * A_LD + xr_c[t] * 4, v);
        }
#pragma unroll
        for (int t = 0; t < 3; t++)
            *(uint4*)(st + OFF_B + (wb_r[t] * B_LD + wb_u[t] * 8) * 2) =
                *(const uint4*)(g_Wh + (size_t)wb_r[t] * 192 + wb_u[t] * 8);
    }
    __syncthreads();

    for (int c = 0; c < 12; c++) {
        char* st  = smem + (c & 1) * STAGE;
        char* nst = smem + ((c + 1) & 1) * STAGE;
        const int k1 = (c + 1) * 32;
        const bool more = (c + 1 < 12);

        // global prefetch of chunk c+1
        float4 xr[2];
        uint4 wr[3];
        if (more) {
#pragma unroll
            for (int t = 0; t < 2; t++)
                xr[t] = *(const float4*)(x + (size_t)(rowBase + xr_r[t]) * C + k1 + xr_c[t] * 4);
#pragma unroll
            for (int t = 0; t < 3; t++)
                wr[t] = *(const uint4*)(g_Wh + (size_t)(k1 + wb_r[t]) * 192 + wb_u[t] * 8);
        }

        // compute chunk c: 12 mma/warp
        const __half* A  = (const __half*)(st + OFF_A);
        const __half* Bs = (const __half*)(st + OFF_B);
#pragma unroll
        for (int ks = 0; ks < 2; ks++) {
            wmma::fragment<wmma::matrix_a, 16, 16, 16, __half, wmma::row_major> af[2];
#pragma unroll
            for (int i = 0; i < 2; i++)
                wmma::load_matrix_sync(af[i], A + (warp_m * 32 + i * 16) * A_LD + ks * 16, A_LD);
#pragma unroll
            for (int j = 0; j < 3; j++) {
                int col = warp_n * 48 + j * 16;
                wmma::fragment<wmma::matrix_b, 16, 16, 16, __half, wmma::row_major> bf;
                wmma::load_matrix_sync(bf, Bs + ks * 16 * B_LD + col, B_LD);
#pragma unroll
                for (int i = 0; i < 2; i++)
                    wmma::mma_sync(acc[i][j], af[i], bf, acc[i][j]);
            }
        }

        // store prefetched chunk into the other stage
        if (more) {
#pragma unroll
            for (int t = 0; t < 2; t++)
                cvt_store4_h(nst + OFF_A, xr_r[t] * A_LD + xr_c[t] * 4, xr[t]);
#pragma unroll
            for (int t = 0; t < 3; t++)
                *(uint4*)(nst + OFF_B + (wb_r[t] * B_LD + wb_u[t] * 8) * 2) = wr[t];
        }
        __syncthreads();
    }

    // ---- epilogue: stage fp32 in smem (single pass, 64 rows), write fp16 ------
    float* Sb = (float*)smem;
#pragma unroll
    for (int i = 0; i < 2; i++)
#pragma unroll
        for (int j = 0; j < 3; j++)
            wmma::store_matrix_sync(
                Sb + (warp_m * 32 + i * 16) * 192 + warp_n * 48 + j * 16,
                acc[i][j], 192, wmma::mem_row_major);
    __syncthreads();

#pragma unroll
    for (int t = 0; t < 24; t++) {
        int f = tid + t * 256;       // 0..6143 element pairs
        int r = f / 96;
        int pc = f - r * 96;
        int cc = pc * 2;             // even col 0..190
        float2 v = *(const float2*)(Sb + r * 192 + cc);
        int col = cc & 63;
        size_t off = (size_t)(rowBase + r) * HS + col;
        if (cc < 64) {
            __half2 hp = __floats2half2_rn(v.x, v.y);
            *(__half2*)(g_Qf + off) = hp;
        } else {
            __half* dhi = (cc < 128) ? g_Khi : g_Vhi;
            __half* dlo = (cc < 128) ? g_Klo : g_Vlo;
            __half h0 = __float2half(v.x);
            __half h1 = __float2half(v.y);
            __half2 hp; hp.x = h0; hp.y = h1;
            __half2 lp;
            lp.x = __float2half(v.x - __half2float(h0));
            lp.y = __float2half(v.y - __half2float(h1));
            *(__half2*)(dhi + off) = hp;
            *(__half2*)(dlo + off) = lp;
        }
    }
}

// ---------------- attention v7: 64x64 tiles, 2 CTAs/SM (unchanged) ------------
static constexpr int LDH = 72;
static constexpr int AOF_QF  = 0;              // 64*72*2 = 9216
static constexpr int AOF_KHI = 9216;
static constexpr int AOF_KLO = 18432;
static constexpr int AOF_VHI = 27648;
static constexpr int AOF_VLO = 36864;
static constexpr int AOF_S   = 46080;          // 64*72*4 = 18432
static constexpr int AOF_PF  = 64512;          // 9216
static constexpr int AOF_L   = 73728;          // 256
static constexpr int ATTN_SMEM = 73984;

__global__ __launch_bounds__(512, 2) void attn_wmma(float* __restrict__ out)
{
    extern __shared__ char smem[];
    __half* Qf  = (__half*)(smem + AOF_QF);
    __half* Khi = (__half*)(smem + AOF_KHI);
    __half* Klo = (__half*)(smem + AOF_KLO);
    __half* Vhi = (__half*)(smem + AOF_VHI);
    __half* Vlo = (__half*)(smem + AOF_VLO);
    float*  S   = (float*)(smem + AOF_S);
    __half* Pf  = (__half*)(smem + AOF_PF);
    float*  lbuf = (float*)(smem + AOF_L);

    const int qt  = blockIdx.x;        // 0..3
    const int b   = blockIdx.y;        // 0..511
    const int i0  = qt * 64;
    const int tid = threadIdx.x;
    const int wid = tid >> 5;
    const int rt  = wid >> 2;          // warp row-tile 0..3
    const int ct  = wid & 3;           // warp col-tile 0..3

    if (tid < 64) lbuf[tid] = 0.0f;

    // load Q tile [64 x 64] fp16: 512 uint4, 1/thread
    {
        const uint4* Qg = (const uint4*)(g_Qf + ((size_t)b * T + i0) * HS);
        int r = tid >> 3, c8 = tid & 7;
        *(uint4*)(Qf + r * LDH + c8 * 8) = Qg[tid];
    }
    __syncthreads();

    wmma::fragment<wmma::accumulator, 16, 16, 16, float> oacc;
    wmma::fill_fragment(oacc, 0.0f);

    const float log2e_scale = 1.4426950408889634f * 0.125f;
    const int nkt = qt + 1;
    const int r_exp  = tid >> 3;
    const int cg     = tid & 7;
    const int i_glob = i0 + r_exp;

    for (int kt = 0; kt < nkt; kt++) {
        const int j0 = kt * 64;

        {
            const uint4* srcs[4] = {
                (const uint4*)(g_Khi + ((size_t)b * T + j0) * HS),
                (const uint4*)(g_Klo + ((size_t)b * T + j0) * HS),
                (const uint4*)(g_Vhi + ((size_t)b * T + j0) * HS),
                (const uint4*)(g_Vlo + ((size_t)b * T + j0) * HS)
            };
            __half* dsts[4] = { Khi, Klo, Vhi, Vlo };
#pragma unroll
            for (int t = 0; t < 4; t++) {
                int f = tid + t * 512;
                int sel = f >> 9;
                int g = f & 511;
                int r = g >> 3, c8 = g & 7;
                *(uint4*)(dsts[sel] + r * LDH + c8 * 8) = srcs[sel][g];
            }
        }
        __syncthreads();

        // ---- S = Qf K^T ----
        {
            const int n = ct * 16;
            wmma::fragment<wmma::accumulator, 16, 16, 16, float> sacc;
            wmma::fill_fragment(sacc, 0.0f);
#pragma unroll
            for (int ks = 0; ks < 4; ks++) {
                wmma::fragment<wmma::matrix_a, 16, 16, 16, __half, wmma::row_major> aq;
                wmma::fragment<wmma::matrix_b, 16, 16, 16, __half, wmma::col_major> bh, bl;
                wmma::load_matrix_sync(aq, Qf + rt * 16 * LDH + ks * 16, LDH);
                wmma::load_matrix_sync(bh, Khi + n * LDH + ks * 16, LDH);
                wmma::load_matrix_sync(bl, Klo + n * LDH + ks * 16, LDH);
                wmma::mma_sync(sacc, aq, bh, sacc);
                wmma::mma_sync(sacc, aq, bl, sacc);
            }
            wmma::store_matrix_sync(S + rt * 16 * LDH + n, sacc, LDH,
                                    wmma::mem_row_major);
        }
        __syncthreads();

        // ---- exp + causal mask + row sums + Pf fp16 ----
        {
            const float* srow = S + r_exp * LDH + cg * 8;
            float ps = 0.0f;
            float p[8];
#pragma unroll
            for (int c = 0; c < 8; c++) {
                int j = j0 + cg * 8 + c;
                p[c] = (j <= i_glob) ? exp2f(srow[c] * log2e_scale) : 0.0f;
                ps += p[c];
            }
            __half2 h0 = __floats2half2_rn(p[0], p[1]);
            __half2 h1 = __floats2half2_rn(p[2], p[3]);
            __half2 h2 = __floats2half2_rn(p[4], p[5]);
            __half2 h3 = __floats2half2_rn(p[6], p[7]);
            uint4 u;
            u.x = *(uint32_t*)&h0; u.y = *(uint32_t*)&h1;
            u.z = *(uint32_t*)&h2; u.w = *(uint32_t*)&h3;
            *(uint4*)(Pf + r_exp * LDH + cg * 8) = u;
            ps += __shfl_xor_sync(0xFFFFFFFFu, ps, 1);
            ps += __shfl_xor_sync(0xFFFFFFFFu, ps, 2);
            ps += __shfl_xor_sync(0xFFFFFFFFu, ps, 4);
            if (cg == 0) lbuf[r_exp] += ps;
        }
        __syncthreads();

        // ---- O += Pf V ----
        {
            const int n = ct * 16;
#pragma unroll
            for (int ks = 0; ks < 4; ks++) {
                wmma::fragment<wmma::matrix_a, 16, 16, 16, __half, wmma::row_major> ap;
                wmma::fragment<wmma::matrix_b, 16, 16, 16, __half, wmma::row_major> bh, bl;
                wmma::load_matrix_sync(ap, Pf + rt * 16 * LDH + ks * 16, LDH);
                wmma::load_matrix_sync(bh, Vhi + ks * 16 * LDH + n, LDH);
                wmma::load_matrix_sync(bl, Vlo + ks * 16 * LDH + n, LDH);
                wmma::mma_sync(oacc, ap, bh, oacc);
                wmma::mma_sync(oacc, ap, bl, oacc);
            }
        }
        __syncthreads();
    }

    // ---- epilogue: normalize + write ----
    wmma::store_matrix_sync(S + rt * 16 * LDH + ct * 16, oacc, LDH,
                            wmma::mem_row_major);
    __syncthreads();
    {
        const float inv = 1.0f / lbuf[r_exp];
        const float* srow = S + r_exp * LDH + cg * 8;
        float* og = out + ((size_t)b * T + i0 + r_exp) * HS + cg * 8;
        float4 v0 = *(const float4*)(srow);
        float4 v1 = *(const float4*)(srow + 4);
        *(float4*)(og)     = make_float4(v0.x * inv, v0.y * inv, v0.z * inv, v0.w * inv);
        *(float4*)(og + 4) = make_float4(v1.x * inv, v1.y * inv, v1.z * inv, v1.w * inv);
    }
}

// ---------------- launch --------------------------------------------------------
extern "C" void kernel_launch(void* const* d_in, const int* in_sizes, int n_in,
                              void* d_out, int out_size)
{
    (void)in_sizes; (void)n_in; (void)out_size;
    const float* x  = (const float*)d_in[0];
    const float* Wq = (const float*)d_in[1];
    const float* Wk = (const float*)d_in[2];
    const float* Wv = (const float*)d_in[3];
    float* out = (float*)d_out;

    convert_w<<<C, 192>>>(Wq, Wk, Wv);

    cudaFuncSetAttribute(qkv_gemm_wmma, cudaFuncAttributeMaxDynamicSharedMemorySize,
                         GEMM_SMEM);
    qkv_gemm_wmma<<<BT / 64, 256, GEMM_SMEM>>>(x);

    cudaFuncSetAttribute(attn_wmma, cudaFuncAttributeMaxDynamicSharedMemorySize,
                         ATTN_SMEM);
    dim3 agrid(4, B);
    attn_wmma<<<agrid, 512, ATTN_SMEM>>>(out);
}

// round 15
// speedup vs baseline: 2.3963x; 1.1396x over previous
#include <cuda_runtime.h>
#include <cuda_fp16.h>
#include <mma.h>
#include <cstdint>

using namespace nvcuda;

#define B 512
#define T 256
#define C 384
#define HS 64
#define BT (B * T)

// ---------------- scratch -----------------------------------------------------
__device__ __half g_Qf[BT * HS];           // Q single fp16
__device__ __half g_Kf[BT * HS];           // K single fp16
__device__ __half g_Vf[BT * HS];           // V single fp16
// fp16 single weights, [k][n] row-major, n in [0,192) = [Wq|Wk|Wv] columns
__device__ __half g_Wh[C * 192];

// ---------------- W fp16 kernel -------------------------------------------------
__global__ void convert_w(const float* __restrict__ Wq,
                          const float* __restrict__ Wk,
                          const float* __restrict__ Wv)
{
    int k = blockIdx.x;     // 0..383
    int n = threadIdx.x;    // 0..191
    const float* W = (n < 64) ? Wq : ((n < 128) ? Wk : Wv);
    g_Wh[(size_t)k * 192 + n] = __float2half(W[(size_t)k * HS + (n & 63)]);
}

// convert float4 -> 4 single fp16, store 8 bytes
__device__ __forceinline__ void cvt_store4_h(char* base, int elemOff, float4 v)
{
    __half2 h01 = __floats2half2_rn(v.x, v.y);
    __half2 h23 = __floats2half2_rn(v.z, v.w);
    uint2 u;
    u.x = *(uint32_t*)&h01;
    u.y = *(uint32_t*)&h23;
    *(uint2*)((__half*)base + elemOff) = u;
}

// ---------------- QKV GEMM: WMMA pure fp16, tile 64x192, 2 CTAs/SM -------------
// 256 threads = 8 warps (2M x 4N), warp tile 32x48. BK=32, 12 chunks.
static constexpr int A_LD = 40;
static constexpr int B_LD = 200;
static constexpr int OFF_A = 0;            // 64*40*2 = 5120
static constexpr int OFF_B = 5120;         // 32*200*2 = 12800
static constexpr int STAGE = 17920;
static constexpr int GEMM_SMEM = 49152;    // epilogue staging 64*192*4 dominates

__global__ __launch_bounds__(256, 2) void qkv_gemm_wmma(const float* __restrict__ x)
{
    extern __shared__ char smem[];
    const int tid = threadIdx.x;
    const int wid = tid >> 5;
    const int warp_m = wid >> 2;       // 0..1 -> rows 32*warp_m
    const int warp_n = wid & 3;        // 0..3 -> cols 48*warp_n
    const int rowBase = blockIdx.x * 64;

    // x: 64 rows x 8 float4 = 512 -> 2/thread
    const int xr_r[2] = { (tid + 0) >> 3, (tid + 256) >> 3 };
    const int xr_c[2] = { (tid + 0) & 7,  (tid + 256) & 7 };
    // W fp16: 32 rows x 24 uint4 = 768 -> 3/thread
    int wb_r[3], wb_u[3];
#pragma unroll
    for (int t = 0; t < 3; t++) {
        int f = tid + t * 256;
        wb_r[t] = f / 24;
        wb_u[t] = f - wb_r[t] * 24;
    }

    wmma::fragment<wmma::accumulator, 16, 16, 16, float> acc[2][3];
#pragma unroll
    for (int i = 0; i < 2; i++)
#pragma unroll
        for (int j = 0; j < 3; j++) wmma::fill_fragment(acc[i][j], 0.0f);

    // ---- prologue: chunk 0 into stage 0 ----
    {
        char* st = smem;
#pragma unroll
        for (int t = 0; t < 2; t++) {
            float4 v = *(const float4*)(x + (size_t)(rowBase + xr_r[t]) * C + xr_c[t] * 4);
            cvt_store4_h(st + OFF_A, xr_r[t] * A_LD + xr_c[t] * 4, v);
        }
#pragma unroll
        for (int t = 0; t < 3; t++)
            *(uint4*)(st + OFF_B + (wb_r[t] * B_LD + wb_u[t] * 8) * 2) =
                *(const uint4*)(g_Wh + (size_t)wb_r[t] * 192 + wb_u[t] * 8);
    }
    __syncthreads();

    for (int c = 0; c < 12; c++) {
        char* st  = smem + (c & 1) * STAGE;
        char* nst = smem + ((c + 1) & 1) * STAGE;
        const int k1 = (c + 1) * 32;
        const bool more = (c + 1 < 12);

        // global prefetch of chunk c+1
        float4 xr[2];
        uint4 wr[3];
        if (more) {
#pragma unroll
            for (int t = 0; t < 2; t++)
                xr[t] = *(const float4*)(x + (size_t)(rowBase + xr_r[t]) * C + k1 + xr_c[t] * 4);
#pragma unroll
            for (int t = 0; t < 3; t++)
                wr[t] = *(const uint4*)(g_Wh + (size_t)(k1 + wb_r[t]) * 192 + wb_u[t] * 8);
        }

        // compute chunk c: 12 mma/warp
        const __half* A  = (const __half*)(st + OFF_A);
        const __half* Bs = (const __half*)(st + OFF_B);
#pragma unroll
        for (int ks = 0; ks < 2; ks++) {
            wmma::fragment<wmma::matrix_a, 16, 16, 16, __half, wmma::row_major> af[2];
#pragma unroll
            for (int i = 0; i < 2; i++)
                wmma::load_matrix_sync(af[i], A + (warp_m * 32 + i * 16) * A_LD + ks * 16, A_LD);
#pragma unroll
            for (int j = 0; j < 3; j++) {
                int col = warp_n * 48 + j * 16;
                wmma::fragment<wmma::matrix_b, 16, 16, 16, __half, wmma::row_major> bf;
                wmma::load_matrix_sync(bf, Bs + ks * 16 * B_LD + col, B_LD);
#pragma unroll
                for (int i = 0; i < 2; i++)
                    wmma::mma_sync(acc[i][j], af[i], bf, acc[i][j]);
            }
        }

        // store prefetched chunk into the other stage
        if (more) {
#pragma unroll
            for (int t = 0; t < 2; t++)
                cvt_store4_h(nst + OFF_A, xr_r[t] * A_LD + xr_c[t] * 4, xr[t]);
#pragma unroll
            for (int t = 0; t < 3; t++)
                *(uint4*)(nst + OFF_B + (wb_r[t] * B_LD + wb_u[t] * 8) * 2) = wr[t];
        }
        __syncthreads();
    }

    // ---- epilogue: stage fp32 in smem (single pass), write single fp16 --------
    float* Sb = (float*)smem;
#pragma unroll
    for (int i = 0; i < 2; i++)
#pragma unroll
        for (int j = 0; j < 3; j++)
            wmma::store_matrix_sync(
                Sb + (warp_m * 32 + i * 16) * 192 + warp_n * 48 + j * 16,
                acc[i][j], 192, wmma::mem_row_major);
    __syncthreads();

#pragma unroll
    for (int t = 0; t < 24; t++) {
        int f = tid + t * 256;       // 0..6143 element pairs
        int r = f / 96;
        int pc = f - r * 96;
        int cc = pc * 2;             // even col 0..190
        float2 v = *(const float2*)(Sb + r * 192 + cc);
        int col = cc & 63;
        size_t off = (size_t)(rowBase + r) * HS + col;
        __half* dst = (cc < 64) ? g_Qf : ((cc < 128) ? g_Kf : g_Vf);
        __half2 hp = __floats2half2_rn(v.x, v.y);
        *(__half2*)(dst + off) = hp;
    }
}

// ---------------- attention v8: 64x64 tiles, 1-product fp16, 2 CTAs/SM --------
static constexpr int LDH = 72;
static constexpr int AOF_QF = 0;               // 64*72*2 = 9216
static constexpr int AOF_KF = 9216;
static constexpr int AOF_VF = 18432;
static constexpr int AOF_S  = 27648;           // 64*72*4 = 18432
static constexpr int AOF_PF = 46080;           // 9216
static constexpr int AOF_L  = 55296;           // 256
static constexpr int ATTN_SMEM = 55552;

__global__ __launch_bounds__(512, 2) void attn_wmma(float* __restrict__ out)
{
    extern __shared__ char smem[];
    __half* Qf  = (__half*)(smem + AOF_QF);
    __half* Kf  = (__half*)(smem + AOF_KF);
    __half* Vf  = (__half*)(smem + AOF_VF);
    float*  S   = (float*)(smem + AOF_S);
    __half* Pf  = (__half*)(smem + AOF_PF);
    float*  lbuf = (float*)(smem + AOF_L);

    const int qt  = blockIdx.x;        // 0..3
    const int b   = blockIdx.y;        // 0..511
    const int i0  = qt * 64;
    const int tid = threadIdx.x;
    const int wid = tid >> 5;
    const int rt  = wid >> 2;          // warp row-tile 0..3
    const int ct  = wid & 3;           // warp col-tile 0..3

    if (tid < 64) lbuf[tid] = 0.0f;

    // load Q tile [64 x 64] fp16: 512 uint4, 1/thread
    {
        const uint4* Qg = (const uint4*)(g_Qf + ((size_t)b * T + i0) * HS);
        int r = tid >> 3, c8 = tid & 7;
        *(uint4*)(Qf + r * LDH + c8 * 8) = Qg[tid];
    }
    __syncthreads();

    wmma::fragment<wmma::accumulator, 16, 16, 16, float> oacc;
    wmma::fill_fragment(oacc, 0.0f);

    const float log2e_scale = 1.4426950408889634f * 0.125f;
    const int nkt = qt + 1;
    const int r_exp  = tid >> 3;
    const int cg     = tid & 7;
    const int i_glob = i0 + r_exp;

    for (int kt = 0; kt < nkt; kt++) {
        const int j0 = kt * 64;

        // load K,V tiles: 2 x 512 uint4 = 1024, 2/thread
        {
            const uint4* Kg = (const uint4*)(g_Kf + ((size_t)b * T + j0) * HS);
            const uint4* Vg = (const uint4*)(g_Vf + ((size_t)b * T + j0) * HS);
            int r0 = tid >> 3, c80 = tid & 7;
            *(uint4*)(Kf + r0 * LDH + c80 * 8) = Kg[tid];
            *(uint4*)(Vf + r0 * LDH + c80 * 8) = Vg[tid];
        }
        __syncthreads();

        // ---- S = Qf Kf^T : 4 mma/warp ----
        {
            const int n = ct * 16;
            wmma::fragment<wmma::accumulator, 16, 16, 16, float> sacc;
            wmma::fill_fragment(sacc, 0.0f);
#pragma unroll
            for (int ks = 0; ks < 4; ks++) {
                wmma::fragment<wmma::matrix_a, 16, 16, 16, __half, wmma::row_major> aq;
                wmma::fragment<wmma::matrix_b, 16, 16, 16, __half, wmma::col_major> bk;
                wmma::load_matrix_sync(aq, Qf + rt * 16 * LDH + ks * 16, LDH);
                wmma::load_matrix_sync(bk, Kf + n * LDH + ks * 16, LDH);
                wmma::mma_sync(sacc, aq, bk, sacc);
            }
            wmma::store_matrix_sync(S + rt * 16 * LDH + n, sacc, LDH,
                                    wmma::mem_row_major);
        }
        __syncthreads();

        // ---- exp + causal mask + row sums + Pf fp16 ----
        {
            const float* srow = S + r_exp * LDH + cg * 8;
            float ps = 0.0f;
            float p[8];
#pragma unroll
            for (int c = 0; c < 8; c++) {
                int j = j0 + cg * 8 + c;
                p[c] = (j <= i_glob) ? exp2f(srow[c] * log2e_scale) : 0.0f;
                ps += p[c];
            }
            __half2 h0 = __floats2half2_rn(p[0], p[1]);
            __half2 h1 = __floats2half2_rn(p[2], p[3]);
            __half2 h2 = __floats2half2_rn(p[4], p[5]);
            __half2 h3 = __floats2half2_rn(p[6], p[7]);
            uint4 u;
            u.x = *(uint32_t*)&h0; u.y = *(uint32_t*)&h1;
            u.z = *(uint32_t*)&h2; u.w = *(uint32_t*)&h3;
            *(uint4*)(Pf + r_exp * LDH + cg * 8) = u;
            ps += __shfl_xor_sync(0xFFFFFFFFu, ps, 1);
            ps += __shfl_xor_sync(0xFFFFFFFFu, ps, 2);
            ps += __shfl_xor_sync(0xFFFFFFFFu, ps, 4);
            if (cg == 0) lbuf[r_exp] += ps;
        }
        __syncthreads();

        // ---- O += Pf Vf : 4 mma/warp ----
        {
            const int n = ct * 16;
#pragma unroll
            for (int ks = 0; ks < 4; ks++) {
                wmma::fragment<wmma::matrix_a, 16, 16, 16, __half, wmma::row_major> ap;
                wmma::fragment<wmma::matrix_b, 16, 16, 16, __half, wmma::row_major> bv;
                wmma::load_matrix_sync(ap, Pf + rt * 16 * LDH + ks * 16, LDH);
                wmma::load_matrix_sync(bv, Vf + ks * 16 * LDH + n, LDH);
                wmma::mma_sync(oacc, ap, bv, oacc);
            }
        }
        __syncthreads();
    }

    // ---- epilogue: normalize + write ----
    wmma::store_matrix_sync(S + rt * 16 * LDH + ct * 16, oacc, LDH,
                            wmma::mem_row_major);
    __syncthreads();
    {
        const float inv = 1.0f / lbuf[r_exp];
        const float* srow = S + r_exp * LDH + cg * 8;
        float* og = out + ((size_t)b * T + i0 + r_exp) * HS + cg * 8;
        float4 v0 = *(const float4*)(srow);
        float4 v1 = *(const float4*)(srow + 4);
        *(float4*)(og)     = make_float4(v0.x * inv, v0.y * inv, v0.z * inv, v0.w * inv);
        *(float4*)(og + 4) = make_float4(v1.x * inv, v1.y * inv, v1.z * inv, v1.w * inv);
    }
}

// ---------------- launch --------------------------------------------------------
extern "C" void kernel_launch(void* const* d_in, const int* in_sizes, int n_in,
                              void* d_out, int out_size)
{
    (void)in_sizes; (void)n_in; (void)out_size;
    const float* x  = (const float*)d_in[0];
    const float* Wq = (const float*)d_in[1];
    const float* Wk = (const float*)d_in[2];
    const float* Wv = (const float*)d_in[3];
    float* out = (float*)d_out;

    convert_w<<<C, 192>>>(Wq, Wk, Wv);

    cudaFuncSetAttribute(qkv_gemm_wmma, cudaFuncAttributeMaxDynamicSharedMemorySize,
                         GEMM_SMEM);
    qkv_gemm_wmma<<<BT / 64, 256, GEMM_SMEM>>>(x);

    cudaFuncSetAttribute(attn_wmma, cudaFuncAttributeMaxDynamicSharedMemorySize,
                         ATTN_SMEM);
    dim3 agrid(4, B);
    attn_wmma<<<agrid, 512, ATTN_SMEM>>>(out);
}

// round 16
// speedup vs baseline: 2.5199x; 1.0516x over previous
#include <cuda_runtime.h>
#include <cuda_fp16.h>
#include <mma.h>
#include <cstdint>

using namespace nvcuda;

#define B 512
#define T 256
#define C 384
#define HS 64
#define BT (B * T)

// ---------------- scratch -----------------------------------------------------
__device__ __half g_Qf[BT * HS];           // Q single fp16
__device__ __half g_Kf[BT * HS];           // K single fp16
__device__ __half g_Vf[BT * HS];           // V single fp16
// fp16 single weights, [k][n] row-major, n in [0,192) = [Wq|Wk|Wv] columns
__device__ __half g_Wh[C * 192];

// ---------------- helpers -------------------------------------------------------
__device__ __forceinline__ uint32_t smem_u32(const void* p) {
    uint32_t a;
    asm("{ .reg .u64 t; cvta.to.shared.u64 t, %1; cvt.u32.u64 %0, t; }"
        : "=r"(a) : "l"(p));
    return a;
}
__device__ __forceinline__ void cp_async16(uint32_t dst_smem, const void* src) {
    asm volatile("cp.async.cg.shared.global [%0], [%1], 16;"
                 :: "r"(dst_smem), "l"(src));
}
__device__ __forceinline__ void cp_async_commit() {
    asm volatile("cp.async.commit_group;");
}
__device__ __forceinline__ void cp_async_wait0() {
    asm volatile("cp.async.wait_group 0;" ::: "memory");
}

// ---------------- W fp16 kernel -------------------------------------------------
__global__ void convert_w(const float* __restrict__ Wq,
                          const float* __restrict__ Wk,
                          const float* __restrict__ Wv)
{
    int k = blockIdx.x;     // 0..383
    int n = threadIdx.x;    // 0..191
    const float* W = (n < 64) ? Wq : ((n < 128) ? Wk : Wv);
    g_Wh[(size_t)k * 192 + n] = __float2half(W[(size_t)k * HS + (n & 63)]);
}

// convert float4 -> 4 single fp16, store 8 bytes
__device__ __forceinline__ void cvt_store4_h(char* base, int elemOff, float4 v)
{
    __half2 h01 = __floats2half2_rn(v.x, v.y);
    __half2 h23 = __floats2half2_rn(v.z, v.w);
    uint2 u;
    u.x = *(uint32_t*)&h01;
    u.y = *(uint32_t*)&h23;
    *(uint2*)((__half*)base + elemOff) = u;
}

// ---------------- QKV GEMM: WMMA fp16, tile 64x192, BK=64, cp.async W ----------
// 256 threads = 8 warps (2M x 4N), warp tile 32x48. 6 K-chunks, double-buffered.
static constexpr int A_LD = 72;            // 64 data cols + 8 pad
static constexpr int B_LD = 200;           // 192 data cols + 8 pad
static constexpr int OFF_A = 0;            // 64*72*2  = 9216
static constexpr int OFF_B = 9216;         // 64*200*2 = 25600
static constexpr int STAGE = 34816;
static constexpr int GEMM_SMEM = 2 * STAGE;   // 69632 (epilogue 49152 fits inside)

__global__ __launch_bounds__(256, 2) void qkv_gemm_wmma(const float* __restrict__ x)
{
    extern __shared__ char smem[];
    const uint32_t smem_base = smem_u32(smem);
    const int tid = threadIdx.x;
    const int wid = tid >> 5;
    const int warp_m = wid >> 2;       // 0..1 -> rows 32*warp_m
    const int warp_n = wid & 3;        // 0..3 -> cols 48*warp_n
    const int rowBase = blockIdx.x * 64;

    // x: 64 rows x 16 float4 = 1024 -> 4/thread
    int xr_r[4], xr_c[4];
#pragma unroll
    for (int t = 0; t < 4; t++) {
        int f = tid + t * 256;
        xr_r[t] = f >> 4;
        xr_c[t] = f & 15;
    }
    // W: 64 rows x 24 uint4 = 1536 -> 6/thread (cp.async)
    int wb_r[6], wb_u[6];
#pragma unroll
    for (int t = 0; t < 6; t++) {
        int f = tid + t * 256;
        wb_r[t] = f / 24;
        wb_u[t] = f - wb_r[t] * 24;
    }

    wmma::fragment<wmma::accumulator, 16, 16, 16, float> acc[2][3];
#pragma unroll
    for (int i = 0; i < 2; i++)
#pragma unroll
        for (int j = 0; j < 3; j++) wmma::fill_fragment(acc[i][j], 0.0f);

    // ---- prologue: chunk 0 into stage 0 ----
    {
        char* st = smem;
        const uint32_t stB = smem_base + OFF_B;
#pragma unroll
        for (int t = 0; t < 6; t++)
            cp_async16(stB + (wb_r[t] * B_LD + wb_u[t] * 8) * 2,
                       g_Wh + (size_t)wb_r[t] * 192 + wb_u[t] * 8);
        cp_async_commit();
#pragma unroll
        for (int t = 0; t < 4; t++) {
            float4 v = *(const float4*)(x + (size_t)(rowBase + xr_r[t]) * C + xr_c[t] * 4);
            cvt_store4_h(st + OFF_A, xr_r[t] * A_LD + xr_c[t] * 4, v);
        }
        cp_async_wait0();
    }
    __syncthreads();

    for (int c = 0; c < 6; c++) {
        char* st  = smem + (c & 1) * STAGE;
        char* nst = smem + ((c + 1) & 1) * STAGE;
        const uint32_t nstB = smem_base + ((c + 1) & 1) * STAGE + OFF_B;
        const int k1 = (c + 1) * 64;
        const bool more = (c + 1 < 6);

        // issue cp.async for next W chunk immediately (overlaps with compute)
        if (more) {
#pragma unroll
            for (int t = 0; t < 6; t++)
                cp_async16(nstB + (wb_r[t] * B_LD + wb_u[t] * 8) * 2,
                           g_Wh + (size_t)(k1 + wb_r[t]) * 192 + wb_u[t] * 8);
            cp_async_commit();
        }

        // prefetch next x chunk into regs
        float4 xr[4];
        if (more) {
#pragma unroll
            for (int t = 0; t < 4; t++)
                xr[t] = *(const float4*)(x + (size_t)(rowBase + xr_r[t]) * C + k1 + xr_c[t] * 4);
        }

        // compute chunk c: 4 ks x (2 A-frag, 3 B-frag, 6 mma)
        const __half* A  = (const __half*)(st + OFF_A);
        const __half* Bs = (const __half*)(st + OFF_B);
#pragma unroll
        for (int ks = 0; ks < 4; ks++) {
            wmma::fragment<wmma::matrix_a, 16, 16, 16, __half, wmma::row_major> af[2];
#pragma unroll
            for (int i = 0; i < 2; i++)
                wmma::load_matrix_sync(af[i], A + (warp_m * 32 + i * 16) * A_LD + ks * 16, A_LD);
#pragma unroll
            for (int j = 0; j < 3; j++) {
                int col = warp_n * 48 + j * 16;
                wmma::fragment<wmma::matrix_b, 16, 16, 16, __half, wmma::row_major> bf;
                wmma::load_matrix_sync(bf, Bs + ks * 16 * B_LD + col, B_LD);
#pragma unroll
                for (int i = 0; i < 2; i++)
                    wmma::mma_sync(acc[i][j], af[i], bf, acc[i][j]);
            }
        }

        // store prefetched x into the other stage
        if (more) {
#pragma unroll
            for (int t = 0; t < 4; t++)
                cvt_store4_h(nst + OFF_A, xr_r[t] * A_LD + xr_c[t] * 4, xr[t]);
            cp_async_wait0();
        }
        __syncthreads();
    }

    // ---- epilogue: stage fp32 in smem (single pass), write single fp16 --------
    float* Sb = (float*)smem;
#pragma unroll
    for (int i = 0; i < 2; i++)
#pragma unroll
        for (int j = 0; j < 3; j++)
            wmma::store_matrix_sync(
                Sb + (warp_m * 32 + i * 16) * 192 + warp_n * 48 + j * 16,
                acc[i][j], 192, wmma::mem_row_major);
    __syncthreads();

#pragma unroll
    for (int t = 0; t < 24; t++) {
        int f = tid + t * 256;       // 0..6143 element pairs
        int r = f / 96;
        int pc = f - r * 96;
        int cc = pc * 2;             // even col 0..190
        float2 v = *(const float2*)(Sb + r * 192 + cc);
        int col = cc & 63;
        size_t off = (size_t)(rowBase + r) * HS + col;
        __half* dst = (cc < 64) ? g_Qf : ((cc < 128) ? g_Kf : g_Vf);
        __half2 hp = __floats2half2_rn(v.x, v.y);
        *(__half2*)(dst + off) = hp;
    }
}

// ---------------- attention v8: 64x64 tiles, 1-product fp16 (unchanged) --------
static constexpr int LDH = 72;
static constexpr int AOF_QF = 0;               // 64*72*2 = 9216
static constexpr int AOF_KF = 9216;
static constexpr int AOF_VF = 18432;
static constexpr int AOF_S  = 27648;           // 64*72*4 = 18432
static constexpr int AOF_PF = 46080;           // 9216
static constexpr int AOF_L  = 55296;           // 256
static constexpr int ATTN_SMEM = 55552;

__global__ __launch_bounds__(512, 2) void attn_wmma(float* __restrict__ out)
{
    extern __shared__ char smem[];
    __half* Qf  = (__half*)(smem + AOF_QF);
    __half* Kf  = (__half*)(smem + AOF_KF);
    __half* Vf  = (__half*)(smem + AOF_VF);
    float*  S   = (float*)(smem + AOF_S);
    __half* Pf  = (__half*)(smem + AOF_PF);
    float*  lbuf = (float*)(smem + AOF_L);

    const int qt  = blockIdx.x;        // 0..3
    const int b   = blockIdx.y;        // 0..511
    const int i0  = qt * 64;
    const int tid = threadIdx.x;
    const int wid = tid >> 5;
    const int rt  = wid >> 2;          // warp row-tile 0..3
    const int ct  = wid & 3;           // warp col-tile 0..3

    if (tid < 64) lbuf[tid] = 0.0f;

    // load Q tile [64 x 64] fp16: 512 uint4, 1/thread
    {
        const uint4* Qg = (const uint4*)(g_Qf + ((size_t)b * T + i0) * HS);
        int r = tid >> 3, c8 = tid & 7;
        *(uint4*)(Qf + r * LDH + c8 * 8) = Qg[tid];
    }
    __syncthreads();

    wmma::fragment<wmma::accumulator, 16, 16, 16, float> oacc;
    wmma::fill_fragment(oacc, 0.0f);

    const float log2e_scale = 1.4426950408889634f * 0.125f;
    const int nkt = qt + 1;
    const int r_exp  = tid >> 3;
    const int cg     = tid & 7;
    const int i_glob = i0 + r_exp;

    for (int kt = 0; kt < nkt; kt++) {
        const int j0 = kt * 64;

        // load K,V tiles: 2 x 512 uint4 = 1024, 2/thread
        {
            const uint4* Kg = (const uint4*)(g_Kf + ((size_t)b * T + j0) * HS);
            const uint4* Vg = (const uint4*)(g_Vf + ((size_t)b * T + j0) * HS);
            int r0 = tid >> 3, c80 = tid & 7;
            *(uint4*)(Kf + r0 * LDH + c80 * 8) = Kg[tid];
            *(uint4*)(Vf + r0 * LDH + c80 * 8) = Vg[tid];
        }
        __syncthreads();

        // ---- S = Qf Kf^T : 4 mma/warp ----
        {
            const int n = ct * 16;
            wmma::fragment<wmma::accumulator, 16, 16, 16, float> sacc;
            wmma::fill_fragment(sacc, 0.0f);
#pragma unroll
            for (int ks = 0; ks < 4; ks++) {
                wmma::fragment<wmma::matrix_a, 16, 16, 16, __half, wmma::row_major> aq;
                wmma::fragment<wmma::matrix_b, 16, 16, 16, __half, wmma::col_major> bk;
                wmma::load_matrix_sync(aq, Qf + rt * 16 * LDH + ks * 16, LDH);
                wmma::load_matrix_sync(bk, Kf + n * LDH + ks * 16, LDH);
                wmma::mma_sync(sacc, aq, bk, sacc);
            }
            wmma::store_matrix_sync(S + rt * 16 * LDH + n, sacc, LDH,
                                    wmma::mem_row_major);
        }
        __syncthreads();

        // ---- exp + causal mask + row sums + Pf fp16 ----
        {
            const float* srow = S + r_exp * LDH + cg * 8;
            float ps = 0.0f;
            float p[8];
#pragma unroll
            for (int c = 0; c < 8; c++) {
                int j = j0 + cg * 8 + c;
                p[c] = (j <= i_glob) ? exp2f(srow[c] * log2e_scale) : 0.0f;
                ps += p[c];
            }
            __half2 h0 = __floats2half2_rn(p[0], p[1]);
            __half2 h1 = __floats2half2_rn(p[2], p[3]);
            __half2 h2 = __floats2half2_rn(p[4], p[5]);
            __half2 h3 = __floats2half2_rn(p[6], p[7]);
            uint4 u;
            u.x = *(uint32_t*)&h0; u.y = *(uint32_t*)&h1;
            u.z = *(uint32_t*)&h2; u.w = *(uint32_t*)&h3;
            *(uint4*)(Pf + r_exp * LDH + cg * 8) = u;
            ps += __shfl_xor_sync(0xFFFFFFFFu, ps, 1);
            ps += __shfl_xor_sync(0xFFFFFFFFu, ps, 2);
            ps += __shfl_xor_sync(0xFFFFFFFFu, ps, 4);
            if (cg == 0) lbuf[r_exp] += ps;
        }
        __syncthreads();

        // ---- O += Pf Vf : 4 mma/warp ----
        {
            const int n = ct * 16;
#pragma unroll
            for (int ks = 0; ks < 4; ks++) {
                wmma::fragment<wmma::matrix_a, 16, 16, 16, __half, wmma::row_major> ap;
                wmma::fragment<wmma::matrix_b, 16, 16, 16, __half, wmma::row_major> bv;
                wmma::load_matrix_sync(ap, Pf + rt * 16 * LDH + ks * 16, LDH);
                wmma::load_matrix_sync(bv, Vf + ks * 16 * LDH + n, LDH);
                wmma::mma_sync(oacc, ap, bv, oacc);
            }
        }
        __syncthreads();
    }

    // ---- epilogue: normalize + write ----
    wmma::store_matrix_sync(S + rt * 16 * LDH + ct * 16, oacc, LDH,
                            wmma::mem_row_major);
    __syncthreads();
    {
        const float inv = 1.0f / lbuf[r_exp];
        const float* srow = S + r_exp * LDH + cg * 8;
        float* og = out + ((size_t)b * T + i0 + r_exp) * HS + cg * 8;
        float4 v0 = *(const float4*)(srow);
        float4 v1 = *(const float4*)(srow + 4);
        *(float4*)(og)     = make_float4(v0.x * inv, v0.y * inv, v0.z * inv, v0.w * inv);
        *(float4*)(og + 4) = make_float4(v1.x * inv, v1.y * inv, v1.z * inv, v1.w * inv);
    }
}

// ---------------- launch --------------------------------------------------------
extern "C" void kernel_launch(void* const* d_in, const int* in_sizes, int n_in,
                              void* d_out, int out_size)
{
    (void)in_sizes; (void)n_in; (void)out_size;
    const float* x  = (const float*)d_in[0];
    const float* Wq = (const float*)d_in[1];
    const float* Wk = (const float*)d_in[2];
    const float* Wv = (const float*)d_in[3];
    float* out = (float*)d_out;

    convert_w<<<C, 192>>>(Wq, Wk, Wv);

    cudaFuncSetAttribute(qkv_gemm_wmma, cudaFuncAttributeMaxDynamicSharedMemorySize,
                         GEMM_SMEM);
    qkv_gemm_wmma<<<BT / 64, 256, GEMM_SMEM>>>(x);

    cudaFuncSetAttribute(attn_wmma, cudaFuncAttributeMaxDynamicSharedMemorySize,
                         ATTN_SMEM);
    dim3 agrid(4, B);
    attn_wmma<<<agrid, 512, ATTN_SMEM>>>(out);
}